// round 1
// baseline (speedup 1.0000x reference)
#include <cuda_runtime.h>
#include <math_constants.h>
#include <cstdint>

#define N_NODES 50000
#define F_IN    256
#define H_DIM   128
#define C_DIM   64
#define E_MAX   1600000
#define NEG_SLOPE 0.2f
#define EPS_F 1e-16f

// ---------------- scratch (device globals; no allocation allowed) ----------
__device__ float g_xl1[N_NODES * H_DIM];
__device__ float g_xr1[N_NODES * H_DIM];
__device__ float g_h  [N_NODES * H_DIM];   // layer1 output / layer2 input (also scatter acc)
__device__ float g_xl2[N_NODES * C_DIM];
__device__ float g_xr2[N_NODES * C_DIM];
__device__ float g_e  [E_MAX];             // per-edge logit, then per-edge exp value
__device__ float g_m1 [N_NODES];
__device__ float g_s1 [N_NODES];
__device__ float g_m2 [N_NODES];
__device__ float g_s2 [N_NODES];

// ---------------- helpers ---------------------------------------------------
__device__ __forceinline__ void atomicMaxFloat(float* addr, float value) {
    // standard sign-split trick; addr must be initialized to -inf (0xFF800000)
    if (value >= 0.0f) {
        atomicMax((int*)addr, __float_as_int(value));
    } else {
        atomicMin((unsigned int*)addr, (unsigned int)__float_as_int(value));
    }
}

__device__ __forceinline__ void redAddV4(float* addr, float a, float b, float c, float d) {
    asm volatile("red.global.add.v4.f32 [%0], {%1, %2, %3, %4};"
                 :: "l"(addr), "f"(a), "f"(b), "f"(c), "f"(d) : "memory");
}
__device__ __forceinline__ void redAddV2(float* addr, float a, float b) {
    asm volatile("red.global.add.v2.f32 [%0], {%1, %2};"
                 :: "l"(addr), "f"(a), "f"(b) : "memory");
}

// ---------------- init: zero accumulators, -inf maxima ----------------------
__global__ void init_kernel(float* __restrict__ out) {
    int i = blockIdx.x * blockDim.x + threadIdx.x;
    int stride = gridDim.x * blockDim.x;
    for (int j = i; j < N_NODES * H_DIM; j += stride) g_h[j] = 0.0f;
    for (int j = i; j < N_NODES * C_DIM; j += stride) out[j] = 0.0f;
    for (int j = i; j < N_NODES; j += stride) {
        g_s1[j] = 0.0f; g_s2[j] = 0.0f;
        g_m1[j] = -CUDART_INF_F; g_m2[j] = -CUDART_INF_F;
    }
}

// ---------------- SGEMM: C = A[M,K] @ B[K,N], dual-weight via blockIdx.z ----
template<int BM, int BN, int BK, int TM, int TN>
__global__ void sgemm_dual(const float* __restrict__ A,
                           const float* __restrict__ Bl, const float* __restrict__ Br,
                           float* __restrict__ Cl, float* __restrict__ Cr,
                           int M, int N, int K) {
    constexpr int THREADS = (BM / TM) * (BN / TN);
    const float* B = blockIdx.z ? Br : Bl;
    float* C       = blockIdx.z ? Cr : Cl;

    __shared__ float As[BK][BM + 4];   // transposed A tile, padded
    __shared__ float Bs[BK][BN];

    const int tid  = threadIdx.x;
    const int tcol = tid % (BN / TN);
    const int trow = tid / (BN / TN);
    const int row0 = blockIdx.y * BM;
    const int col0 = blockIdx.x * BN;

    float acc[TM][TN];
    #pragma unroll
    for (int i = 0; i < TM; i++)
        #pragma unroll
        for (int j = 0; j < TN; j++) acc[i][j] = 0.0f;

    constexpr int A_F4 = BM * BK / 4;
    constexpr int A_IT = A_F4 / THREADS;
    constexpr int B_F4 = BK * BN / 4;
    constexpr int B_IT = (B_F4 + THREADS - 1) / THREADS;

    for (int k0 = 0; k0 < K; k0 += BK) {
        #pragma unroll
        for (int l = 0; l < A_IT; l++) {
            int fid = tid + l * THREADS;
            int ar  = fid / (BK / 4);
            int ac4 = fid % (BK / 4);
            float4 v = make_float4(0.f, 0.f, 0.f, 0.f);
            int grow = row0 + ar;
            if (grow < M)
                v = *(const float4*)(A + (size_t)grow * K + k0 + ac4 * 4);
            As[ac4 * 4 + 0][ar] = v.x;
            As[ac4 * 4 + 1][ar] = v.y;
            As[ac4 * 4 + 2][ar] = v.z;
            As[ac4 * 4 + 3][ar] = v.w;
        }
        #pragma unroll
        for (int l = 0; l < B_IT; l++) {
            int fid = tid + l * THREADS;
            if (fid < B_F4) {
                int br  = fid / (BN / 4);
                int bc4 = fid % (BN / 4);
                float4 v = *(const float4*)(B + (size_t)(k0 + br) * N + col0 + bc4 * 4);
                *(float4*)(&Bs[br][bc4 * 4]) = v;
            }
        }
        __syncthreads();

        #pragma unroll
        for (int k = 0; k < BK; k++) {
            float a[TM], b[TN];
            #pragma unroll
            for (int i = 0; i < TM; i++) a[i] = As[k][trow * TM + i];
            #pragma unroll
            for (int j = 0; j < TN; j++) b[j] = Bs[k][tcol * TN + j];
            #pragma unroll
            for (int i = 0; i < TM; i++)
                #pragma unroll
                for (int j = 0; j < TN; j++)
                    acc[i][j] = fmaf(a[i], b[j], acc[i][j]);
        }
        __syncthreads();
    }

    #pragma unroll
    for (int i = 0; i < TM; i++) {
        int grow = row0 + trow * TM + i;
        if (grow < M) {
            #pragma unroll
            for (int j = 0; j < TN; j += 4) {
                float4 v = make_float4(acc[i][j], acc[i][j+1], acc[i][j+2], acc[i][j+3]);
                *(float4*)(C + (size_t)grow * N + col0 + tcol * TN + j) = v;
            }
        }
    }
}

// ---------------- edge pass 1: per-edge logit + segment max -----------------
// one warp per edge; F in {128, 64}
template<int F>
__global__ void edge_logit_kernel(const int* __restrict__ src, const int* __restrict__ dst,
                                  const float* __restrict__ xl, const float* __restrict__ xr,
                                  const float* __restrict__ att,
                                  float* __restrict__ e_out, float* __restrict__ m, int E) {
    int gw   = (blockIdx.x * blockDim.x + threadIdx.x) >> 5;
    int lane = threadIdx.x & 31;
    if (gw >= E) return;
    int sn = src[gw], dn = dst[gw];
    float sum = 0.0f;
    if (F == 128) {
        float4 a = ((const float4*)xl)[(size_t)sn * 32 + lane];
        float4 b = ((const float4*)xr)[(size_t)dn * 32 + lane];
        float4 w = ((const float4*)att)[lane];
        float z;
        z = a.x + b.x; sum = fmaf(w.x, (z > 0.f ? z : NEG_SLOPE * z), sum);
        z = a.y + b.y; sum = fmaf(w.y, (z > 0.f ? z : NEG_SLOPE * z), sum);
        z = a.z + b.z; sum = fmaf(w.z, (z > 0.f ? z : NEG_SLOPE * z), sum);
        z = a.w + b.w; sum = fmaf(w.w, (z > 0.f ? z : NEG_SLOPE * z), sum);
    } else {
        float2 a = ((const float2*)xl)[(size_t)sn * 32 + lane];
        float2 b = ((const float2*)xr)[(size_t)dn * 32 + lane];
        float2 w = ((const float2*)att)[lane];
        float z;
        z = a.x + b.x; sum = fmaf(w.x, (z > 0.f ? z : NEG_SLOPE * z), sum);
        z = a.y + b.y; sum = fmaf(w.y, (z > 0.f ? z : NEG_SLOPE * z), sum);
    }
    #pragma unroll
    for (int o = 16; o > 0; o >>= 1) sum += __shfl_xor_sync(0xFFFFFFFFu, sum, o);
    if (lane == 0) {
        e_out[gw] = sum;
        atomicMaxFloat(m + dn, sum);
    }
}

// ---------------- edge pass 2: exp(e - m[dst]) + segment sum ----------------
__global__ void edge_exp_kernel(const int* __restrict__ dst, float* __restrict__ ea,
                                const float* __restrict__ m, float* __restrict__ s, int E) {
    int i = blockIdx.x * blockDim.x + threadIdx.x;
    if (i >= E) return;
    int dn = dst[i];
    float a = expf(ea[i] - m[dn]);
    ea[i] = a;
    atomicAdd(s + dn, a);
}

// ---------------- edge pass 3: out[dst] += alpha * xl[src] ------------------
template<int F>
__global__ void edge_scatter_kernel(const int* __restrict__ src, const int* __restrict__ dst,
                                    const float* __restrict__ a, const float* __restrict__ s,
                                    const float* __restrict__ xl, float* __restrict__ out, int E) {
    int gw   = (blockIdx.x * blockDim.x + threadIdx.x) >> 5;
    int lane = threadIdx.x & 31;
    if (gw >= E) return;
    int sn = src[gw], dn = dst[gw];
    float alpha = a[gw] / (s[dn] + EPS_F);
    if (F == 128) {
        float4 v = ((const float4*)xl)[(size_t)sn * 32 + lane];
        redAddV4(out + (size_t)dn * F + lane * 4,
                 alpha * v.x, alpha * v.y, alpha * v.z, alpha * v.w);
    } else {
        float2 v = ((const float2*)xl)[(size_t)sn * 32 + lane];
        redAddV2(out + (size_t)dn * F + lane * 2, alpha * v.x, alpha * v.y);
    }
}

// ---------------- finalize --------------------------------------------------
__global__ void finalize1_kernel(const float* __restrict__ b1) {
    int i = blockIdx.x * blockDim.x + threadIdx.x;
    if (i >= N_NODES * H_DIM) return;
    float v = g_h[i] + b1[i % H_DIM];
    g_h[i] = v > 0.f ? v : 0.f;
}
__global__ void finalize2_kernel(float* __restrict__ out, const float* __restrict__ b2) {
    int i = blockIdx.x * blockDim.x + threadIdx.x;
    if (i >= N_NODES * C_DIM) return;
    out[i] = out[i] + b2[i % C_DIM];
}

// ---------------- launch ----------------------------------------------------
extern "C" void kernel_launch(void* const* d_in, const int* in_sizes, int n_in,
                              void* d_out, int out_size) {
    const float* x    = (const float*)d_in[0];
    const int*   ei   = (const int*)  d_in[1];
    const float* Wl1  = (const float*)d_in[2];
    const float* Wr1  = (const float*)d_in[3];
    const float* att1 = (const float*)d_in[4];
    const float* b1   = (const float*)d_in[5];
    const float* Wl2  = (const float*)d_in[6];
    const float* Wr2  = (const float*)d_in[7];
    const float* att2 = (const float*)d_in[8];
    const float* b2   = (const float*)d_in[9];
    float* out = (float*)d_out;

    const int E = in_sizes[1] / 2;
    const int* src = ei;
    const int* dst = ei + E;

    float *p_xl1, *p_xr1, *p_h, *p_xl2, *p_xr2, *p_e, *p_m1, *p_s1, *p_m2, *p_s2;
    cudaGetSymbolAddress((void**)&p_xl1, g_xl1);
    cudaGetSymbolAddress((void**)&p_xr1, g_xr1);
    cudaGetSymbolAddress((void**)&p_h,   g_h);
    cudaGetSymbolAddress((void**)&p_xl2, g_xl2);
    cudaGetSymbolAddress((void**)&p_xr2, g_xr2);
    cudaGetSymbolAddress((void**)&p_e,   g_e);
    cudaGetSymbolAddress((void**)&p_m1,  g_m1);
    cudaGetSymbolAddress((void**)&p_s1,  g_s1);
    cudaGetSymbolAddress((void**)&p_m2,  g_m2);
    cudaGetSymbolAddress((void**)&p_s2,  g_s2);

    // init accumulators
    init_kernel<<<512, 256>>>(out);

    // ---- layer 1 ----
    {
        dim3 grid(1, (N_NODES + 127) / 128, 2);
        sgemm_dual<128, 128, 16, 8, 8><<<grid, 256>>>(
            x, Wl1, Wr1, p_xl1, p_xr1, N_NODES, H_DIM, F_IN);
    }
    {
        int blocks = (E + 7) / 8;  // 8 warps / block
        edge_logit_kernel<128><<<blocks, 256>>>(src, dst, p_xl1, p_xr1, att1, p_e, p_m1, E);
        edge_exp_kernel<<<(E + 255) / 256, 256>>>(dst, p_e, p_m1, p_s1, E);
        edge_scatter_kernel<128><<<blocks, 256>>>(src, dst, p_e, p_s1, p_xl1, p_h, E);
    }
    finalize1_kernel<<<(N_NODES * H_DIM + 255) / 256, 256>>>(b1);

    // ---- layer 2 ----
    {
        dim3 grid(1, (N_NODES + 127) / 128, 2);
        sgemm_dual<128, 64, 16, 8, 4><<<grid, 256>>>(
            p_h, Wl2, Wr2, p_xl2, p_xr2, N_NODES, C_DIM, H_DIM);
    }
    {
        int blocks = (E + 7) / 8;
        edge_logit_kernel<64><<<blocks, 256>>>(src, dst, p_xl2, p_xr2, att2, p_e, p_m2, E);
        edge_exp_kernel<<<(E + 255) / 256, 256>>>(dst, p_e, p_m2, p_s2, E);
        edge_scatter_kernel<64><<<blocks, 256>>>(src, dst, p_e, p_s2, p_xl2, out, E);
    }
    finalize2_kernel<<<(N_NODES * C_DIM + 255) / 256, 256>>>(out, b2);
}

// round 2
// speedup vs baseline: 1.7729x; 1.7729x over previous
#include <cuda_runtime.h>
#include <math_constants.h>
#include <cstdint>

#define N_NODES 50000
#define F_IN    256
#define H_DIM   128
#define C_DIM   64
#define E_MAX   1600000
#define NEG_SLOPE 0.2f
#define EPS_F 1e-16f

// ---------------- scratch (device globals; no allocation allowed) ----------
__device__ float g_xl1[N_NODES * H_DIM];
__device__ float g_xr1[N_NODES * H_DIM];
__device__ float g_h  [N_NODES * H_DIM];   // layer1 output / layer2 input
__device__ float g_xl2[N_NODES * C_DIM];
__device__ float g_xr2[N_NODES * C_DIM];
__device__ int   g_deg[N_NODES];
__device__ int   g_rowptr[N_NODES + 1];
__device__ int   g_wp [N_NODES];
__device__ int   g_csrc[E_MAX];            // src ids grouped by dst

// ---------------- CSR build -------------------------------------------------
__global__ void zero_deg_kernel() {
    int i = blockIdx.x * blockDim.x + threadIdx.x;
    if (i < N_NODES) g_deg[i] = 0;
}

__global__ void hist_kernel(const int* __restrict__ dst, int E) {
    int i = blockIdx.x * blockDim.x + threadIdx.x;
    if (i < E) atomicAdd(&g_deg[dst[i]], 1);
}

// single-block inclusive->exclusive scan over N_NODES degrees
__global__ void scan_kernel(int E) {
    __shared__ int sh[1024];
    __shared__ int carry_sh;
    if (threadIdx.x == 0) carry_sh = 0;
    __syncthreads();
    for (int base = 0; base < N_NODES; base += 1024) {
        int i = base + (int)threadIdx.x;
        int v = (i < N_NODES) ? g_deg[i] : 0;
        sh[threadIdx.x] = v;
        __syncthreads();
        #pragma unroll
        for (int off = 1; off < 1024; off <<= 1) {
            int t = (threadIdx.x >= off) ? sh[threadIdx.x - off] : 0;
            __syncthreads();
            sh[threadIdx.x] += t;
            __syncthreads();
        }
        int incl = sh[threadIdx.x] + carry_sh;
        int excl = incl - v;
        if (i < N_NODES) { g_rowptr[i] = excl; g_wp[i] = excl; }
        __syncthreads();
        if (threadIdx.x == 1023) carry_sh = incl;
        __syncthreads();
    }
    if (threadIdx.x == 0) g_rowptr[N_NODES] = E;
}

__global__ void scatter_kernel(const int* __restrict__ src, const int* __restrict__ dst, int E) {
    int i = blockIdx.x * blockDim.x + threadIdx.x;
    if (i >= E) return;
    int pos = atomicAdd(&g_wp[dst[i]], 1);
    g_csrc[pos] = src[i];
}

// ---------------- SGEMM: C = A[M,K] @ B[K,N], dual-weight via blockIdx.z ----
template<int BM, int BN, int BK, int TM, int TN>
__global__ void sgemm_dual(const float* __restrict__ A,
                           const float* __restrict__ Bl, const float* __restrict__ Br,
                           float* __restrict__ Cl, float* __restrict__ Cr,
                           int M, int N, int K) {
    constexpr int THREADS = (BM / TM) * (BN / TN);
    const float* B = blockIdx.z ? Br : Bl;
    float* C       = blockIdx.z ? Cr : Cl;

    __shared__ float As[BK][BM + 4];
    __shared__ float Bs[BK][BN];

    const int tid  = threadIdx.x;
    const int tcol = tid % (BN / TN);
    const int trow = tid / (BN / TN);
    const int row0 = blockIdx.y * BM;
    const int col0 = blockIdx.x * BN;

    float acc[TM][TN];
    #pragma unroll
    for (int i = 0; i < TM; i++)
        #pragma unroll
        for (int j = 0; j < TN; j++) acc[i][j] = 0.0f;

    constexpr int A_F4 = BM * BK / 4;
    constexpr int A_IT = A_F4 / THREADS;
    constexpr int B_F4 = BK * BN / 4;
    constexpr int B_IT = (B_F4 + THREADS - 1) / THREADS;

    for (int k0 = 0; k0 < K; k0 += BK) {
        #pragma unroll
        for (int l = 0; l < A_IT; l++) {
            int fid = tid + l * THREADS;
            int ar  = fid / (BK / 4);
            int ac4 = fid % (BK / 4);
            float4 v = make_float4(0.f, 0.f, 0.f, 0.f);
            int grow = row0 + ar;
            if (grow < M)
                v = *(const float4*)(A + (size_t)grow * K + k0 + ac4 * 4);
            As[ac4 * 4 + 0][ar] = v.x;
            As[ac4 * 4 + 1][ar] = v.y;
            As[ac4 * 4 + 2][ar] = v.z;
            As[ac4 * 4 + 3][ar] = v.w;
        }
        #pragma unroll
        for (int l = 0; l < B_IT; l++) {
            int fid = tid + l * THREADS;
            if (fid < B_F4) {
                int br  = fid / (BN / 4);
                int bc4 = fid % (BN / 4);
                float4 v = *(const float4*)(B + (size_t)(k0 + br) * N + col0 + bc4 * 4);
                *(float4*)(&Bs[br][bc4 * 4]) = v;
            }
        }
        __syncthreads();

        #pragma unroll
        for (int k = 0; k < BK; k++) {
            float a[TM], b[TN];
            #pragma unroll
            for (int i = 0; i < TM; i++) a[i] = As[k][trow * TM + i];
            #pragma unroll
            for (int j = 0; j < TN; j++) b[j] = Bs[k][tcol * TN + j];
            #pragma unroll
            for (int i = 0; i < TM; i++)
                #pragma unroll
                for (int j = 0; j < TN; j++)
                    acc[i][j] = fmaf(a[i], b[j], acc[i][j]);
        }
        __syncthreads();
    }

    #pragma unroll
    for (int i = 0; i < TM; i++) {
        int grow = row0 + trow * TM + i;
        if (grow < M) {
            #pragma unroll
            for (int j = 0; j < TN; j += 4) {
                float4 v = make_float4(acc[i][j], acc[i][j+1], acc[i][j+2], acc[i][j+3]);
                *(float4*)(C + (size_t)grow * N + col0 + tcol * TN + j) = v;
            }
        }
    }
}

// ---------------- fused GATv2 edge phase: one warp per dst node --------------
// exp without max-shift (logits are O(1), exp overflow impossible);
// mathematically identical to reference softmax.
template<int F, bool RELU>
__global__ void gat_aggregate_kernel(const float* __restrict__ xl,
                                     const float* __restrict__ xr,
                                     const float* __restrict__ att,
                                     const float* __restrict__ bias,
                                     float* __restrict__ out) {
    constexpr int VPL = F / 32;   // floats per lane (4 or 2)
    int n    = (blockIdx.x * blockDim.x + threadIdx.x) >> 5;
    int lane = threadIdx.x & 31;
    if (n >= N_NODES) return;

    float xrv[VPL], attv[VPL], acc[VPL];
    #pragma unroll
    for (int k = 0; k < VPL; k++) {
        xrv[k]  = xr[(size_t)n * F + lane * VPL + k];
        attv[k] = att[lane * VPL + k];
        acc[k]  = 0.0f;
    }
    float s = 0.0f;

    int start = g_rowptr[n];
    int end   = g_rowptr[n + 1];

    for (int base = start; base < end; base += 32) {
        int myid = (base + lane < end) ? g_csrc[base + lane] : 0;
        int cnt  = min(32, end - base);
        for (int j = 0; j < cnt; j++) {
            int sn = __shfl_sync(0xFFFFFFFFu, myid, j);
            float v[VPL];
            float partial = 0.0f;
            #pragma unroll
            for (int k = 0; k < VPL; k++) {
                v[k] = __ldg(xl + (size_t)sn * F + lane * VPL + k);
                float z = v[k] + xrv[k];
                float lz = z > 0.0f ? z : NEG_SLOPE * z;
                partial = fmaf(attv[k], lz, partial);
            }
            #pragma unroll
            for (int o = 16; o > 0; o >>= 1)
                partial += __shfl_xor_sync(0xFFFFFFFFu, partial, o);
            float p = expf(partial);
            s += p;
            #pragma unroll
            for (int k = 0; k < VPL; k++)
                acc[k] = fmaf(p, v[k], acc[k]);
        }
    }

    float inv = 1.0f / (s + EPS_F);
    #pragma unroll
    for (int k = 0; k < VPL; k++) {
        float o = acc[k] * inv + bias[lane * VPL + k];
        if (RELU) o = o > 0.0f ? o : 0.0f;
        out[(size_t)n * F + lane * VPL + k] = o;
    }
}

// ---------------- launch ----------------------------------------------------
extern "C" void kernel_launch(void* const* d_in, const int* in_sizes, int n_in,
                              void* d_out, int out_size) {
    const float* x    = (const float*)d_in[0];
    const int*   ei   = (const int*)  d_in[1];
    const float* Wl1  = (const float*)d_in[2];
    const float* Wr1  = (const float*)d_in[3];
    const float* att1 = (const float*)d_in[4];
    const float* b1   = (const float*)d_in[5];
    const float* Wl2  = (const float*)d_in[6];
    const float* Wr2  = (const float*)d_in[7];
    const float* att2 = (const float*)d_in[8];
    const float* b2   = (const float*)d_in[9];
    float* out = (float*)d_out;

    const int E = in_sizes[1] / 2;
    const int* src = ei;
    const int* dst = ei + E;

    float *p_xl1, *p_xr1, *p_h, *p_xl2, *p_xr2;
    cudaGetSymbolAddress((void**)&p_xl1, g_xl1);
    cudaGetSymbolAddress((void**)&p_xr1, g_xr1);
    cudaGetSymbolAddress((void**)&p_h,   g_h);
    cudaGetSymbolAddress((void**)&p_xl2, g_xl2);
    cudaGetSymbolAddress((void**)&p_xr2, g_xr2);

    // ---- CSR build (once; shared by both layers) ----
    zero_deg_kernel<<<(N_NODES + 255) / 256, 256>>>();
    hist_kernel<<<(E + 255) / 256, 256>>>(dst, E);
    scan_kernel<<<1, 1024>>>(E);
    scatter_kernel<<<(E + 255) / 256, 256>>>(src, dst, E);

    // ---- layer 1 ----
    {
        dim3 grid(1, (N_NODES + 127) / 128, 2);
        sgemm_dual<128, 128, 16, 8, 8><<<grid, 256>>>(
            x, Wl1, Wr1, p_xl1, p_xr1, N_NODES, H_DIM, F_IN);
    }
    gat_aggregate_kernel<128, true><<<(N_NODES + 7) / 8, 256>>>(
        p_xl1, p_xr1, att1, b1, p_h);

    // ---- layer 2 ----
    {
        dim3 grid(1, (N_NODES + 127) / 128, 2);
        sgemm_dual<128, 64, 16, 8, 4><<<grid, 256>>>(
            p_h, Wl2, Wr2, p_xl2, p_xr2, N_NODES, C_DIM, H_DIM);
    }
    gat_aggregate_kernel<64, false><<<(N_NODES + 7) / 8, 256>>>(
        p_xl2, p_xr2, att2, b2, out);
}

// round 4
// speedup vs baseline: 2.1526x; 1.2142x over previous
#include <cuda_runtime.h>
#include <cuda_bf16.h>
#include <math_constants.h>
#include <cstdint>

#define N_NODES 50000
#define F_IN    256
#define H_DIM   128
#define C_DIM   64
#define E_MAX   1600000
#define NEG_SLOPE 0.2f
#define EPS_F 1e-16f

// ---------------- scratch (device globals; no allocation allowed) ----------
__device__ float g_xl1[N_NODES * H_DIM];
__device__ float g_xr1[N_NODES * H_DIM];
__device__ float g_h  [N_NODES * H_DIM];   // layer1 output / layer2 input
__device__ float g_xl2[N_NODES * C_DIM];
__device__ float g_xr2[N_NODES * C_DIM];
__device__ int   g_deg[N_NODES];
__device__ int   g_rowptr[N_NODES + 1];
__device__ int   g_wp [N_NODES];
__device__ int   g_csrc[E_MAX];            // src ids grouped by dst

// ==================== small asm helpers =====================================
__device__ __forceinline__ uint32_t smem_to_u32(const void* p) {
    uint32_t a;
    asm("{ .reg .u64 t; cvta.to.shared.u64 t, %1; cvt.u32.u64 %0, t; }"
        : "=r"(a) : "l"(p));
    return a;
}
__device__ __forceinline__ uint32_t lds32(uint32_t a) {
    uint32_t v; asm volatile("ld.shared.b32 %0, [%1];" : "=r"(v) : "r"(a)); return v;
}
__device__ __forceinline__ uint32_t lds16(uint32_t a) {
    uint32_t v; asm volatile("ld.shared.u16 %0, [%1];" : "=r"(v) : "r"(a)); return v;
}
__device__ __forceinline__ void sts32(uint32_t a, uint32_t v) {
    asm volatile("st.shared.b32 [%0], %1;" :: "r"(a), "r"(v) : "memory");
}
__device__ __forceinline__ uint32_t pack_bf16(__nv_bfloat16 a, __nv_bfloat16 b) {
    return (uint32_t)__bfloat16_as_ushort(a) | ((uint32_t)__bfloat16_as_ushort(b) << 16);
}
__device__ __forceinline__ void mma16816(float* c, const uint32_t* a, const uint32_t* b) {
    asm volatile(
        "mma.sync.aligned.m16n8k16.row.col.f32.bf16.bf16.f32 "
        "{%0,%1,%2,%3}, {%4,%5,%6,%7}, {%8,%9}, {%0,%1,%2,%3};"
        : "+f"(c[0]), "+f"(c[1]), "+f"(c[2]), "+f"(c[3])
        : "r"(a[0]), "r"(a[1]), "r"(a[2]), "r"(a[3]), "r"(b[0]), "r"(b[1]));
}

// ==================== bf16x3 tensor-core GEMM (mma.sync) ====================
// C[:, gcol] with [Wl | Wr] fused along N. BM=128, BN=128, BK=64.
// Per-block N window = blockIdx.z * 128.
// A smem: [128][64] bf16 hi/lo, row pitch 144 B.
// B smem: [64][128] bf16 hi/lo, row pitch 272 B (k-major).
template<int KFULL, int NHALF>
__global__ __launch_bounds__(256, 1)
void gemm_mma_bf16x3(const float* __restrict__ A,
                     const float* __restrict__ Wl, const float* __restrict__ Wr,
                     float* __restrict__ Cl, float* __restrict__ Cr, int M) {
    constexpr int NC   = KFULL / 64;
    constexpr uint32_t A_LO = 18432;            // 128*144
    constexpr uint32_t B_HI = 36864;            // A hi+lo
    constexpr uint32_t B_LO = 17408;            // 64*272 (offset from B_HI)
    constexpr uint32_t BUF  = 36864 + 2 * 17408; // 71680

    extern __shared__ char smem[];
    const uint32_t sb = smem_to_u32(smem);

    const int tid = threadIdx.x;
    const int wid = tid >> 5;
    const int l   = tid & 31;
    const int wr  = wid >> 2;          // 0..1
    const int wc  = wid & 3;           // 0..3
    const int m0  = blockIdx.x * 128;
    const int z   = blockIdx.z;

    float acc[4][4][4];
    #pragma unroll
    for (int i = 0; i < 4; i++)
        #pragma unroll
        for (int j = 0; j < 4; j++)
            #pragma unroll
            for (int q = 0; q < 4; q++) acc[i][j][q] = 0.0f;

    auto fillA = [&](int c, uint32_t bufb) {
        const int k0 = c * 64;
        #pragma unroll
        for (int i = 0; i < 8; i++) {
            int fid = tid + i * 256;
            int r   = fid >> 4;
            int c4  = fid & 15;
            float4 v = make_float4(0.f, 0.f, 0.f, 0.f);
            int gr = m0 + r;
            if (gr < M)
                v = *(const float4*)(A + (size_t)gr * KFULL + k0 + c4 * 4);
            __nv_bfloat16 h0 = __float2bfloat16(v.x), h1 = __float2bfloat16(v.y);
            __nv_bfloat16 h2 = __float2bfloat16(v.z), h3 = __float2bfloat16(v.w);
            __nv_bfloat16 l0 = __float2bfloat16(v.x - __bfloat162float(h0));
            __nv_bfloat16 l1 = __float2bfloat16(v.y - __bfloat162float(h1));
            __nv_bfloat16 l2 = __float2bfloat16(v.z - __bfloat162float(h2));
            __nv_bfloat16 l3 = __float2bfloat16(v.w - __bfloat162float(h3));
            uint32_t addr = bufb + (uint32_t)r * 144 + (uint32_t)c4 * 8;
            sts32(addr,            pack_bf16(h0, h1));
            sts32(addr + 4,        pack_bf16(h2, h3));
            sts32(addr + A_LO,     pack_bf16(l0, l1));
            sts32(addr + A_LO + 4, pack_bf16(l2, l3));
        }
    };

    auto fillB = [&](int c, uint32_t bufb) {
        const int k0 = c * 64;
        #pragma unroll
        for (int i = 0; i < 8; i++) {
            int fid = tid + i * 256;
            int k   = fid >> 5;
            int n0  = (fid & 31) * 4;
            int gc  = z * 128 + n0;
            const float* Wp = (gc < NHALF) ? Wl : Wr;
            int col = (gc < NHALF) ? gc : gc - NHALF;
            float4 v = *(const float4*)(Wp + (size_t)(k0 + k) * NHALF + col);
            __nv_bfloat16 h0 = __float2bfloat16(v.x), h1 = __float2bfloat16(v.y);
            __nv_bfloat16 h2 = __float2bfloat16(v.z), h3 = __float2bfloat16(v.w);
            __nv_bfloat16 l0 = __float2bfloat16(v.x - __bfloat162float(h0));
            __nv_bfloat16 l1 = __float2bfloat16(v.y - __bfloat162float(h1));
            __nv_bfloat16 l2 = __float2bfloat16(v.z - __bfloat162float(h2));
            __nv_bfloat16 l3 = __float2bfloat16(v.w - __bfloat162float(h3));
            uint32_t addr = bufb + B_HI + (uint32_t)k * 272 + (uint32_t)n0 * 2;
            sts32(addr,            pack_bf16(h0, h1));
            sts32(addr + 4,        pack_bf16(h2, h3));
            sts32(addr + B_LO,     pack_bf16(l0, l1));
            sts32(addr + B_LO + 4, pack_bf16(l2, l3));
        }
    };

    auto compute = [&](uint32_t bufb) {
        // base addresses for this lane
        const uint32_t aBase = bufb + ((uint32_t)(wr * 64 + (l >> 2))) * 144 + (uint32_t)(l & 3) * 4;
        const uint32_t bBase = bufb + B_HI + ((uint32_t)((l & 3) * 2)) * 272
                             + ((uint32_t)(wc * 32 + (l >> 2))) * 2;
        #pragma unroll
        for (int ks = 0; ks < 4; ks++) {
            uint32_t ah[4][4], al[4][4], bh[4][2], bl[4][2];
            #pragma unroll
            for (int mf = 0; mf < 4; mf++) {
                uint32_t a0 = aBase + (uint32_t)mf * 2304 + (uint32_t)ks * 32;
                ah[mf][0] = lds32(a0);
                ah[mf][1] = lds32(a0 + 1152);
                ah[mf][2] = lds32(a0 + 16);
                ah[mf][3] = lds32(a0 + 1152 + 16);
                al[mf][0] = lds32(a0 + A_LO);
                al[mf][1] = lds32(a0 + A_LO + 1152);
                al[mf][2] = lds32(a0 + A_LO + 16);
                al[mf][3] = lds32(a0 + A_LO + 1152 + 16);
            }
            #pragma unroll
            for (int nf = 0; nf < 4; nf++) {
                uint32_t b0 = bBase + (uint32_t)ks * 4352 + (uint32_t)nf * 16;
                bh[nf][0] = lds16(b0)        | (lds16(b0 + 272)  << 16);
                bh[nf][1] = lds16(b0 + 2176) | (lds16(b0 + 2448) << 16);
                bl[nf][0] = lds16(b0 + B_LO)        | (lds16(b0 + B_LO + 272)  << 16);
                bl[nf][1] = lds16(b0 + B_LO + 2176) | (lds16(b0 + B_LO + 2448) << 16);
            }
            #pragma unroll
            for (int mf = 0; mf < 4; mf++)
                #pragma unroll
                for (int nf = 0; nf < 4; nf++) {
                    mma16816(acc[mf][nf], ah[mf], bh[nf]);
                    mma16816(acc[mf][nf], ah[mf], bl[nf]);
                    mma16816(acc[mf][nf], al[mf], bh[nf]);
                }
        }
    };

    fillA(0, sb); fillB(0, sb);
    __syncthreads();
    #pragma unroll
    for (int c = 0; c < NC; c++) {
        uint32_t cur = sb + (uint32_t)(c & 1) * BUF;
        if (c + 1 < NC) {
            uint32_t nxt = sb + (uint32_t)((c + 1) & 1) * BUF;
            fillA(c + 1, nxt); fillB(c + 1, nxt);
        }
        compute(cur);
        __syncthreads();
    }

    // ---- epilogue ----
    #pragma unroll
    for (int mf = 0; mf < 4; mf++) {
        int r0 = m0 + wr * 64 + mf * 16 + (l >> 2);
        #pragma unroll
        for (int nf = 0; nf < 4; nf++) {
            int colL = wc * 32 + nf * 8 + (l & 3) * 2;
            int gc = z * 128 + colL;
            bool selL = gc < NHALF;
            float* Cp = selL ? Cl : Cr;
            int ch = selL ? gc : gc - NHALF;
            if (r0 < M)
                *(float2*)(Cp + (size_t)r0 * NHALF + ch) =
                    make_float2(acc[mf][nf][0], acc[mf][nf][1]);
            if (r0 + 8 < M)
                *(float2*)(Cp + (size_t)(r0 + 8) * NHALF + ch) =
                    make_float2(acc[mf][nf][2], acc[mf][nf][3]);
        }
    }
}

// ==================== CSR build ==============================================
__global__ void zero_deg_kernel() {
    int i = blockIdx.x * blockDim.x + threadIdx.x;
    if (i < N_NODES) g_deg[i] = 0;
}

__global__ void hist_kernel(const int* __restrict__ dst, int E) {
    int i = blockIdx.x * blockDim.x + threadIdx.x;
    if (i < E) atomicAdd(&g_deg[dst[i]], 1);
}

__global__ void scan_kernel(int E) {
    __shared__ int sh[1024];
    __shared__ int carry_sh;
    if (threadIdx.x == 0) carry_sh = 0;
    __syncthreads();
    for (int base = 0; base < N_NODES; base += 1024) {
        int i = base + (int)threadIdx.x;
        int v = (i < N_NODES) ? g_deg[i] : 0;
        sh[threadIdx.x] = v;
        __syncthreads();
        #pragma unroll
        for (int off = 1; off < 1024; off <<= 1) {
            int t = (threadIdx.x >= off) ? sh[threadIdx.x - off] : 0;
            __syncthreads();
            sh[threadIdx.x] += t;
            __syncthreads();
        }
        int incl = sh[threadIdx.x] + carry_sh;
        int excl = incl - v;
        if (i < N_NODES) { g_rowptr[i] = excl; g_wp[i] = excl; }
        __syncthreads();
        if (threadIdx.x == 1023) carry_sh = incl;
        __syncthreads();
    }
    if (threadIdx.x == 0) g_rowptr[N_NODES] = E;
}

__global__ void scatter_kernel(const int* __restrict__ src, const int* __restrict__ dst, int E) {
    int i = blockIdx.x * blockDim.x + threadIdx.x;
    if (i >= E) return;
    int pos = atomicAdd(&g_wp[dst[i]], 1);
    g_csrc[pos] = src[i];
}

// ==================== fused GATv2 edge phase: one warp per dst node ==========
template<int F, bool RELU>
__global__ void gat_aggregate_kernel(const float* __restrict__ xl,
                                     const float* __restrict__ xr,
                                     const float* __restrict__ att,
                                     const float* __restrict__ bias,
                                     float* __restrict__ out) {
    constexpr int VPL = F / 32;
    int n    = (blockIdx.x * blockDim.x + threadIdx.x) >> 5;
    int lane = threadIdx.x & 31;
    if (n >= N_NODES) return;

    float xrv[VPL], attv[VPL], acc[VPL];
    #pragma unroll
    for (int k = 0; k < VPL; k++) {
        xrv[k]  = xr[(size_t)n * F + lane * VPL + k];
        attv[k] = att[lane * VPL + k];
        acc[k]  = 0.0f;
    }
    float s = 0.0f;

    int start = g_rowptr[n];
    int end   = g_rowptr[n + 1];

    for (int base = start; base < end; base += 32) {
        int myid = (base + lane < end) ? g_csrc[base + lane] : 0;
        int cnt  = min(32, end - base);
        for (int j = 0; j < cnt; j++) {
            int sn = __shfl_sync(0xFFFFFFFFu, myid, j);
            float v[VPL];
            float partial = 0.0f;
            #pragma unroll
            for (int k = 0; k < VPL; k++) {
                v[k] = __ldg(xl + (size_t)sn * F + lane * VPL + k);
                float z = v[k] + xrv[k];
                float lz = z > 0.0f ? z : NEG_SLOPE * z;
                partial = fmaf(attv[k], lz, partial);
            }
            #pragma unroll
            for (int o = 16; o > 0; o >>= 1)
                partial += __shfl_xor_sync(0xFFFFFFFFu, partial, o);
            float p = expf(partial);
            s += p;
            #pragma unroll
            for (int k = 0; k < VPL; k++)
                acc[k] = fmaf(p, v[k], acc[k]);
        }
    }

    float inv = 1.0f / (s + EPS_F);
    #pragma unroll
    for (int k = 0; k < VPL; k++) {
        float o = acc[k] * inv + bias[lane * VPL + k];
        if (RELU) o = o > 0.0f ? o : 0.0f;
        out[(size_t)n * F + lane * VPL + k] = o;
    }
}

// ==================== launch =================================================
extern "C" void kernel_launch(void* const* d_in, const int* in_sizes, int n_in,
                              void* d_out, int out_size) {
    const float* x    = (const float*)d_in[0];
    const int*   ei   = (const int*)  d_in[1];
    const float* Wl1  = (const float*)d_in[2];
    const float* Wr1  = (const float*)d_in[3];
    const float* att1 = (const float*)d_in[4];
    const float* b1   = (const float*)d_in[5];
    const float* Wl2  = (const float*)d_in[6];
    const float* Wr2  = (const float*)d_in[7];
    const float* att2 = (const float*)d_in[8];
    const float* b2   = (const float*)d_in[9];
    float* out = (float*)d_out;

    const int E = in_sizes[1] / 2;
    const int* src = ei;
    const int* dst = ei + E;

    float *p_xl1, *p_xr1, *p_h, *p_xl2, *p_xr2;
    cudaGetSymbolAddress((void**)&p_xl1, g_xl1);
    cudaGetSymbolAddress((void**)&p_xr1, g_xr1);
    cudaGetSymbolAddress((void**)&p_h,   g_h);
    cudaGetSymbolAddress((void**)&p_xl2, g_xl2);
    cudaGetSymbolAddress((void**)&p_xr2, g_xr2);

    const int SMEM = 2 * 71680;  // 143360 bytes (double buffer)
    cudaFuncSetAttribute(gemm_mma_bf16x3<F_IN,  H_DIM>,
                         cudaFuncAttributeMaxDynamicSharedMemorySize, SMEM);
    cudaFuncSetAttribute(gemm_mma_bf16x3<H_DIM, C_DIM>,
                         cudaFuncAttributeMaxDynamicSharedMemorySize, SMEM);

    const int TILES = (N_NODES + 127) / 128;

    // ---- CSR build (once; shared by both layers) ----
    zero_deg_kernel<<<(N_NODES + 255) / 256, 256>>>();
    hist_kernel<<<(E + 255) / 256, 256>>>(dst, E);
    scan_kernel<<<1, 1024>>>(E);
    scatter_kernel<<<(E + 255) / 256, 256>>>(src, dst, E);

    // ---- layer 1 ----
    {
        dim3 grid(TILES, 1, 2);
        gemm_mma_bf16x3<F_IN, H_DIM><<<grid, 256, SMEM>>>(x, Wl1, Wr1, p_xl1, p_xr1, N_NODES);
    }
    gat_aggregate_kernel<128, true><<<(N_NODES + 7) / 8, 256>>>(
        p_xl1, p_xr1, att1, b1, p_h);

    // ---- layer 2 ----
    {
        dim3 grid(TILES, 1, 1);
        gemm_mma_bf16x3<H_DIM, C_DIM><<<grid, 256, SMEM>>>(p_h, Wl2, Wr2, p_xl2, p_xr2, N_NODES);
    }
    gat_aggregate_kernel<64, false><<<(N_NODES + 7) / 8, 256>>>(
        p_xl2, p_xr2, att2, b2, out);
}

// round 5
// speedup vs baseline: 2.8195x; 1.3098x over previous
#include <cuda_runtime.h>
#include <cuda_bf16.h>
#include <cuda_fp16.h>
#include <math_constants.h>
#include <cstdint>

#define N_NODES 50000
#define F_IN    256
#define H_DIM   128
#define C_DIM   64
#define E_MAX   1600000
#define NEG_SLOPE 0.2f
#define EPS_F 1e-16f

// ---------------- scratch (device globals; no allocation allowed) ----------
__device__ __half g_xl1h[N_NODES * H_DIM];   // fp16 source-side features (layer1)
__device__ float  g_xr1 [N_NODES * H_DIM];
__device__ float  g_h   [N_NODES * H_DIM];   // layer1 output / layer2 input
__device__ __half g_xl2h[N_NODES * C_DIM];
__device__ float  g_xr2 [N_NODES * C_DIM];
__device__ int    g_deg[N_NODES];
__device__ int    g_rowptr[N_NODES + 1];
__device__ int    g_wp [N_NODES];
__device__ int    g_csrc[E_MAX];             // src ids grouped by dst

// ==================== small asm helpers =====================================
__device__ __forceinline__ uint32_t smem_to_u32(const void* p) {
    uint32_t a;
    asm("{ .reg .u64 t; cvta.to.shared.u64 t, %1; cvt.u32.u64 %0, t; }"
        : "=r"(a) : "l"(p));
    return a;
}
__device__ __forceinline__ uint32_t lds32(uint32_t a) {
    uint32_t v; asm volatile("ld.shared.b32 %0, [%1];" : "=r"(v) : "r"(a)); return v;
}
__device__ __forceinline__ uint32_t lds16(uint32_t a) {
    uint32_t v; asm volatile("ld.shared.u16 %0, [%1];" : "=r"(v) : "r"(a)); return v;
}
__device__ __forceinline__ void sts32(uint32_t a, uint32_t v) {
    asm volatile("st.shared.b32 [%0], %1;" :: "r"(a), "r"(v) : "memory");
}
__device__ __forceinline__ uint32_t pack_bf16(__nv_bfloat16 a, __nv_bfloat16 b) {
    return (uint32_t)__bfloat16_as_ushort(a) | ((uint32_t)__bfloat16_as_ushort(b) << 16);
}
__device__ __forceinline__ void mma16816(float* c, const uint32_t* a, const uint32_t* b) {
    asm volatile(
        "mma.sync.aligned.m16n8k16.row.col.f32.bf16.bf16.f32 "
        "{%0,%1,%2,%3}, {%4,%5,%6,%7}, {%8,%9}, {%0,%1,%2,%3};"
        : "+f"(c[0]), "+f"(c[1]), "+f"(c[2]), "+f"(c[3])
        : "r"(a[0]), "r"(a[1]), "r"(a[2]), "r"(a[3]), "r"(b[0]), "r"(b[1]));
}

// ==================== bf16x3 tensor-core GEMM (mma.sync) ====================
// Fused [Wl | Wr] along N. BM=128, BN=128, BK=64, z = N-window.
// Left-half (Wl) results stored as fp16 into Hl; right half fp32 into Cr.
template<int KFULL, int NHALF>
__global__ __launch_bounds__(256, 1)
void gemm_mma_bf16x3(const float* __restrict__ A,
                     const float* __restrict__ Wl, const float* __restrict__ Wr,
                     __half* __restrict__ Hl, float* __restrict__ Cr, int M) {
    constexpr int NC   = KFULL / 64;
    constexpr uint32_t A_LO = 18432;             // 128*144
    constexpr uint32_t B_HI = 36864;             // A hi+lo
    constexpr uint32_t B_LO = 17408;             // 64*272
    constexpr uint32_t BUF  = 36864 + 2 * 17408; // 71680

    extern __shared__ char smem[];
    const uint32_t sb = smem_to_u32(smem);

    const int tid = threadIdx.x;
    const int wid = tid >> 5;
    const int l   = tid & 31;
    const int wr  = wid >> 2;
    const int wc  = wid & 3;
    const int m0  = blockIdx.x * 128;
    const int z   = blockIdx.z;

    float acc[4][4][4];
    #pragma unroll
    for (int i = 0; i < 4; i++)
        #pragma unroll
        for (int j = 0; j < 4; j++)
            #pragma unroll
            for (int q = 0; q < 4; q++) acc[i][j][q] = 0.0f;

    auto fillA = [&](int c, uint32_t bufb) {
        const int k0 = c * 64;
        #pragma unroll
        for (int i = 0; i < 8; i++) {
            int fid = tid + i * 256;
            int r   = fid >> 4;
            int c4  = fid & 15;
            float4 v = make_float4(0.f, 0.f, 0.f, 0.f);
            int gr = m0 + r;
            if (gr < M)
                v = *(const float4*)(A + (size_t)gr * KFULL + k0 + c4 * 4);
            __nv_bfloat16 h0 = __float2bfloat16(v.x), h1 = __float2bfloat16(v.y);
            __nv_bfloat16 h2 = __float2bfloat16(v.z), h3 = __float2bfloat16(v.w);
            __nv_bfloat16 l0 = __float2bfloat16(v.x - __bfloat162float(h0));
            __nv_bfloat16 l1 = __float2bfloat16(v.y - __bfloat162float(h1));
            __nv_bfloat16 l2 = __float2bfloat16(v.z - __bfloat162float(h2));
            __nv_bfloat16 l3 = __float2bfloat16(v.w - __bfloat162float(h3));
            uint32_t addr = bufb + (uint32_t)r * 144 + (uint32_t)c4 * 8;
            sts32(addr,            pack_bf16(h0, h1));
            sts32(addr + 4,        pack_bf16(h2, h3));
            sts32(addr + A_LO,     pack_bf16(l0, l1));
            sts32(addr + A_LO + 4, pack_bf16(l2, l3));
        }
    };

    auto fillB = [&](int c, uint32_t bufb) {
        const int k0 = c * 64;
        #pragma unroll
        for (int i = 0; i < 8; i++) {
            int fid = tid + i * 256;
            int k   = fid >> 5;
            int n0  = (fid & 31) * 4;
            int gc  = z * 128 + n0;
            const float* Wp = (gc < NHALF) ? Wl : Wr;
            int col = (gc < NHALF) ? gc : gc - NHALF;
            float4 v = *(const float4*)(Wp + (size_t)(k0 + k) * NHALF + col);
            __nv_bfloat16 h0 = __float2bfloat16(v.x), h1 = __float2bfloat16(v.y);
            __nv_bfloat16 h2 = __float2bfloat16(v.z), h3 = __float2bfloat16(v.w);
            __nv_bfloat16 l0 = __float2bfloat16(v.x - __bfloat162float(h0));
            __nv_bfloat16 l1 = __float2bfloat16(v.y - __bfloat162float(h1));
            __nv_bfloat16 l2 = __float2bfloat16(v.z - __bfloat162float(h2));
            __nv_bfloat16 l3 = __float2bfloat16(v.w - __bfloat162float(h3));
            uint32_t addr = bufb + B_HI + (uint32_t)k * 272 + (uint32_t)n0 * 2;
            sts32(addr,            pack_bf16(h0, h1));
            sts32(addr + 4,        pack_bf16(h2, h3));
            sts32(addr + B_LO,     pack_bf16(l0, l1));
            sts32(addr + B_LO + 4, pack_bf16(l2, l3));
        }
    };

    auto compute = [&](uint32_t bufb) {
        const uint32_t aBase = bufb + ((uint32_t)(wr * 64 + (l >> 2))) * 144 + (uint32_t)(l & 3) * 4;
        const uint32_t bBase = bufb + B_HI + ((uint32_t)((l & 3) * 2)) * 272
                             + ((uint32_t)(wc * 32 + (l >> 2))) * 2;
        #pragma unroll
        for (int ks = 0; ks < 4; ks++) {
            uint32_t ah[4][4], al[4][4], bh[4][2], bl[4][2];
            #pragma unroll
            for (int mf = 0; mf < 4; mf++) {
                uint32_t a0 = aBase + (uint32_t)mf * 2304 + (uint32_t)ks * 32;
                ah[mf][0] = lds32(a0);
                ah[mf][1] = lds32(a0 + 1152);
                ah[mf][2] = lds32(a0 + 16);
                ah[mf][3] = lds32(a0 + 1152 + 16);
                al[mf][0] = lds32(a0 + A_LO);
                al[mf][1] = lds32(a0 + A_LO + 1152);
                al[mf][2] = lds32(a0 + A_LO + 16);
                al[mf][3] = lds32(a0 + A_LO + 1152 + 16);
            }
            #pragma unroll
            for (int nf = 0; nf < 4; nf++) {
                uint32_t b0 = bBase + (uint32_t)ks * 4352 + (uint32_t)nf * 16;
                bh[nf][0] = lds16(b0)        | (lds16(b0 + 272)  << 16);
                bh[nf][1] = lds16(b0 + 2176) | (lds16(b0 + 2448) << 16);
                bl[nf][0] = lds16(b0 + B_LO)        | (lds16(b0 + B_LO + 272)  << 16);
                bl[nf][1] = lds16(b0 + B_LO + 2176) | (lds16(b0 + B_LO + 2448) << 16);
            }
            #pragma unroll
            for (int mf = 0; mf < 4; mf++)
                #pragma unroll
                for (int nf = 0; nf < 4; nf++) {
                    mma16816(acc[mf][nf], ah[mf], bh[nf]);
                    mma16816(acc[mf][nf], ah[mf], bl[nf]);
                    mma16816(acc[mf][nf], al[mf], bh[nf]);
                }
        }
    };

    fillA(0, sb); fillB(0, sb);
    __syncthreads();
    #pragma unroll
    for (int c = 0; c < NC; c++) {
        uint32_t cur = sb + (uint32_t)(c & 1) * BUF;
        if (c + 1 < NC) {
            uint32_t nxt = sb + (uint32_t)((c + 1) & 1) * BUF;
            fillA(c + 1, nxt); fillB(c + 1, nxt);
        }
        compute(cur);
        __syncthreads();
    }

    // ---- epilogue: left half -> fp16 Hl, right half -> fp32 Cr --------------
    #pragma unroll
    for (int mf = 0; mf < 4; mf++) {
        int r0 = m0 + wr * 64 + mf * 16 + (l >> 2);
        #pragma unroll
        for (int nf = 0; nf < 4; nf++) {
            int colL = wc * 32 + nf * 8 + (l & 3) * 2;
            int gc = z * 128 + colL;
            bool selL = gc < NHALF;
            int ch = selL ? gc : gc - NHALF;
            if (r0 < M) {
                if (selL)
                    *(__half2*)(Hl + (size_t)r0 * NHALF + ch) =
                        __floats2half2_rn(acc[mf][nf][0], acc[mf][nf][1]);
                else
                    *(float2*)(Cr + (size_t)r0 * NHALF + ch) =
                        make_float2(acc[mf][nf][0], acc[mf][nf][1]);
            }
            if (r0 + 8 < M) {
                if (selL)
                    *(__half2*)(Hl + (size_t)(r0 + 8) * NHALF + ch) =
                        __floats2half2_rn(acc[mf][nf][2], acc[mf][nf][3]);
                else
                    *(float2*)(Cr + (size_t)(r0 + 8) * NHALF + ch) =
                        make_float2(acc[mf][nf][2], acc[mf][nf][3]);
            }
        }
    }
}

// ==================== CSR build ==============================================
__global__ void zero_deg_kernel() {
    int i = blockIdx.x * blockDim.x + threadIdx.x;
    if (i < N_NODES) g_deg[i] = 0;
}

__global__ void hist_kernel(const int* __restrict__ dst, int E) {
    int i = (blockIdx.x * blockDim.x + threadIdx.x) * 4;
    if (i >= E) return;
    if (i + 4 <= E && ((E & 3) == 0)) {
        int4 d = *(const int4*)(dst + i);
        atomicAdd(&g_deg[d.x], 1);
        atomicAdd(&g_deg[d.y], 1);
        atomicAdd(&g_deg[d.z], 1);
        atomicAdd(&g_deg[d.w], 1);
    } else {
        int e = min(i + 4, E);
        for (; i < e; i++) atomicAdd(&g_deg[dst[i]], 1);
    }
}

// single-block exclusive scan, warp-shuffle based
__global__ void scan_kernel(int E) {
    __shared__ int wsums[32];
    __shared__ int carry_sh;
    const int lane = threadIdx.x & 31;
    const int w    = threadIdx.x >> 5;
    if (threadIdx.x == 0) carry_sh = 0;
    __syncthreads();
    for (int base = 0; base < N_NODES; base += 1024) {
        int i = base + (int)threadIdx.x;
        int v = (i < N_NODES) ? g_deg[i] : 0;
        int x = v;
        #pragma unroll
        for (int o = 1; o < 32; o <<= 1) {
            int t = __shfl_up_sync(0xFFFFFFFFu, x, o);
            if (lane >= o) x += t;
        }
        if (lane == 31) wsums[w] = x;
        __syncthreads();
        if (w == 0) {
            int y = wsums[lane];
            #pragma unroll
            for (int o = 1; o < 32; o <<= 1) {
                int u = __shfl_up_sync(0xFFFFFFFFu, y, o);
                if (lane >= o) y += u;
            }
            wsums[lane] = y;
        }
        __syncthreads();
        int warpoff = (w == 0) ? 0 : wsums[w - 1];
        int incl = x + warpoff + carry_sh;
        if (i < N_NODES) { g_rowptr[i] = incl - v; g_wp[i] = incl - v; }
        __syncthreads();
        if (threadIdx.x == 1023) carry_sh = incl;
        __syncthreads();
    }
    if (threadIdx.x == 0) g_rowptr[N_NODES] = E;
}

__global__ void scatter_kernel(const int* __restrict__ src, const int* __restrict__ dst, int E) {
    int i = (blockIdx.x * blockDim.x + threadIdx.x) * 4;
    if (i >= E) return;
    if (i + 4 <= E && ((E & 3) == 0)) {
        int4 s = *(const int4*)(src + i);
        int4 d = *(const int4*)(dst + i);
        int p0 = atomicAdd(&g_wp[d.x], 1);
        int p1 = atomicAdd(&g_wp[d.y], 1);
        int p2 = atomicAdd(&g_wp[d.z], 1);
        int p3 = atomicAdd(&g_wp[d.w], 1);
        g_csrc[p0] = s.x; g_csrc[p1] = s.y; g_csrc[p2] = s.z; g_csrc[p3] = s.w;
    } else {
        int e = min(i + 4, E);
        for (; i < e; i++) {
            int pos = atomicAdd(&g_wp[dst[i]], 1);
            g_csrc[pos] = src[i];
        }
    }
}

// ==================== fused GATv2 edge phase: one warp per dst node ==========
// xl in fp16 (halved gather traffic), 2-edge interleaved for ILP.
template<int F, bool RELU>
__global__ void gat_aggregate_kernel(const __half* __restrict__ xl,
                                     const float* __restrict__ xr,
                                     const float* __restrict__ att,
                                     const float* __restrict__ bias,
                                     float* __restrict__ out) {
    constexpr int VPL = F / 32;
    int n    = (blockIdx.x * blockDim.x + threadIdx.x) >> 5;
    int lane = threadIdx.x & 31;
    if (n >= N_NODES) return;

    float xrv[VPL], attv[VPL], acc[VPL];
    #pragma unroll
    for (int k = 0; k < VPL; k++) {
        xrv[k]  = xr[(size_t)n * F + lane * VPL + k];
        attv[k] = att[lane * VPL + k];
        acc[k]  = 0.0f;
    }
    float s = 0.0f;

    const int start = g_rowptr[n];
    const int end   = g_rowptr[n + 1];

    auto loadV = [&](int sn, float* v) {
        if (VPL == 4) {
            uint2 u = *(const uint2*)(xl + (size_t)sn * F + lane * 4);
            float2 f01 = __half22float2(*(const __half2*)&u.x);
            float2 f23 = __half22float2(*(const __half2*)&u.y);
            v[0] = f01.x; v[1] = f01.y;
            if (VPL > 2) { v[2] = f23.x; v[3] = f23.y; }
        } else {
            uint32_t u = *(const uint32_t*)(xl + (size_t)sn * F + lane * 2);
            float2 f01 = __half22float2(*(const __half2*)&u);
            v[0] = f01.x; v[1] = f01.y;
        }
    };

    for (int base = start; base < end; base += 32) {
        int myid = (base + lane < end) ? g_csrc[base + lane] : 0;
        int cnt  = min(32, end - base);
        int j = 0;
        for (; j + 2 <= cnt; j += 2) {
            int sn0 = __shfl_sync(0xFFFFFFFFu, myid, j);
            int sn1 = __shfl_sync(0xFFFFFFFFu, myid, j + 1);
            float v0[VPL], v1[VPL];
            loadV(sn0, v0);
            loadV(sn1, v1);
            float p0 = 0.0f, p1 = 0.0f;
            #pragma unroll
            for (int k = 0; k < VPL; k++) {
                float z0 = v0[k] + xrv[k];
                float z1 = v1[k] + xrv[k];
                float lz0 = z0 > 0.0f ? z0 : NEG_SLOPE * z0;
                float lz1 = z1 > 0.0f ? z1 : NEG_SLOPE * z1;
                p0 = fmaf(attv[k], lz0, p0);
                p1 = fmaf(attv[k], lz1, p1);
            }
            #pragma unroll
            for (int o = 16; o > 0; o >>= 1) {
                p0 += __shfl_xor_sync(0xFFFFFFFFu, p0, o);
                p1 += __shfl_xor_sync(0xFFFFFFFFu, p1, o);
            }
            float e0 = __expf(p0);
            float e1 = __expf(p1);
            s += e0 + e1;
            #pragma unroll
            for (int k = 0; k < VPL; k++)
                acc[k] = fmaf(e0, v0[k], fmaf(e1, v1[k], acc[k]));
        }
        if (j < cnt) {
            int sn0 = __shfl_sync(0xFFFFFFFFu, myid, j);
            float v0[VPL];
            loadV(sn0, v0);
            float p0 = 0.0f;
            #pragma unroll
            for (int k = 0; k < VPL; k++) {
                float z0 = v0[k] + xrv[k];
                float lz0 = z0 > 0.0f ? z0 : NEG_SLOPE * z0;
                p0 = fmaf(attv[k], lz0, p0);
            }
            #pragma unroll
            for (int o = 16; o > 0; o >>= 1)
                p0 += __shfl_xor_sync(0xFFFFFFFFu, p0, o);
            float e0 = __expf(p0);
            s += e0;
            #pragma unroll
            for (int k = 0; k < VPL; k++)
                acc[k] = fmaf(e0, v0[k], acc[k]);
        }
    }

    float inv = 1.0f / (s + EPS_F);
    #pragma unroll
    for (int k = 0; k < VPL; k++) {
        float o = acc[k] * inv + bias[lane * VPL + k];
        if (RELU) o = o > 0.0f ? o : 0.0f;
        out[(size_t)n * F + lane * VPL + k] = o;
    }
}

// ==================== launch =================================================
extern "C" void kernel_launch(void* const* d_in, const int* in_sizes, int n_in,
                              void* d_out, int out_size) {
    const float* x    = (const float*)d_in[0];
    const int*   ei   = (const int*)  d_in[1];
    const float* Wl1  = (const float*)d_in[2];
    const float* Wr1  = (const float*)d_in[3];
    const float* att1 = (const float*)d_in[4];
    const float* b1   = (const float*)d_in[5];
    const float* Wl2  = (const float*)d_in[6];
    const float* Wr2  = (const float*)d_in[7];
    const float* att2 = (const float*)d_in[8];
    const float* b2   = (const float*)d_in[9];
    float* out = (float*)d_out;

    const int E = in_sizes[1] / 2;
    const int* src = ei;
    const int* dst = ei + E;

    __half *p_xl1h, *p_xl2h;
    float *p_xr1, *p_h, *p_xr2;
    cudaGetSymbolAddress((void**)&p_xl1h, g_xl1h);
    cudaGetSymbolAddress((void**)&p_xr1,  g_xr1);
    cudaGetSymbolAddress((void**)&p_h,    g_h);
    cudaGetSymbolAddress((void**)&p_xl2h, g_xl2h);
    cudaGetSymbolAddress((void**)&p_xr2,  g_xr2);

    const int SMEM = 2 * 71680;  // double buffer
    cudaFuncSetAttribute(gemm_mma_bf16x3<F_IN,  H_DIM>,
                         cudaFuncAttributeMaxDynamicSharedMemorySize, SMEM);
    cudaFuncSetAttribute(gemm_mma_bf16x3<H_DIM, C_DIM>,
                         cudaFuncAttributeMaxDynamicSharedMemorySize, SMEM);

    const int TILES = (N_NODES + 127) / 128;
    const int Q4 = (E + 3) / 4;

    // ---- CSR build (once; shared by both layers) ----
    zero_deg_kernel<<<(N_NODES + 255) / 256, 256>>>();
    hist_kernel<<<(Q4 + 255) / 256, 256>>>(dst, E);
    scan_kernel<<<1, 1024>>>(E);
    scatter_kernel<<<(Q4 + 255) / 256, 256>>>(src, dst, E);

    // ---- layer 1 ----
    {
        dim3 grid(TILES, 1, 2);
        gemm_mma_bf16x3<F_IN, H_DIM><<<grid, 256, SMEM>>>(x, Wl1, Wr1, p_xl1h, p_xr1, N_NODES);
    }
    gat_aggregate_kernel<128, true><<<(N_NODES + 7) / 8, 256>>>(
        p_xl1h, p_xr1, att1, b1, p_h);

    // ---- layer 2 ----
    {
        dim3 grid(TILES, 1, 1);
        gemm_mma_bf16x3<H_DIM, C_DIM><<<grid, 256, SMEM>>>(p_h, Wl2, Wr2, p_xl2h, p_xr2, N_NODES);
    }
    gat_aggregate_kernel<64, false><<<(N_NODES + 7) / 8, 256>>>(
        p_xl2h, p_xr2, att2, b2, out);
}

// round 6
// speedup vs baseline: 2.9033x; 1.0297x over previous
#include <cuda_runtime.h>
#include <cuda_bf16.h>
#include <cuda_fp16.h>
#include <math_constants.h>
#include <cstdint>

#define N_NODES 50000
#define F_IN    256
#define H_DIM   128
#define C_DIM   64
#define E_MAX   1600000
#define NEG_SLOPE 0.2f
#define EPS_F 1e-16f

// ---------------- scratch (device globals; no allocation allowed) ----------
__device__ __half g_xl1h[N_NODES * H_DIM];   // fp16 source-side features (layer1)
__device__ float  g_xr1 [N_NODES * H_DIM];
__device__ float  g_h   [N_NODES * H_DIM];   // layer1 output / layer2 input
__device__ __half g_xl2h[N_NODES * C_DIM];
__device__ float  g_xr2 [N_NODES * C_DIM];
__device__ int    g_deg[N_NODES];
__device__ int    g_rowptr[N_NODES + 1];
__device__ int    g_wp [N_NODES];
__device__ int    g_csrc[E_MAX];             // src ids grouped by dst

// ==================== small asm helpers =====================================
__device__ __forceinline__ uint32_t smem_to_u32(const void* p) {
    uint32_t a;
    asm("{ .reg .u64 t; cvta.to.shared.u64 t, %1; cvt.u32.u64 %0, t; }"
        : "=r"(a) : "l"(p));
    return a;
}
__device__ __forceinline__ uint32_t lds32(uint32_t a) {
    uint32_t v; asm volatile("ld.shared.b32 %0, [%1];" : "=r"(v) : "r"(a)); return v;
}
__device__ __forceinline__ uint32_t lds16(uint32_t a) {
    uint32_t v; asm volatile("ld.shared.u16 %0, [%1];" : "=r"(v) : "r"(a)); return v;
}
__device__ __forceinline__ void sts32(uint32_t a, uint32_t v) {
    asm volatile("st.shared.b32 [%0], %1;" :: "r"(a), "r"(v) : "memory");
}
__device__ __forceinline__ uint32_t pack_bf16(__nv_bfloat16 a, __nv_bfloat16 b) {
    return (uint32_t)__bfloat16_as_ushort(a) | ((uint32_t)__bfloat16_as_ushort(b) << 16);
}
__device__ __forceinline__ void mma16816(float* c, const uint32_t* a, const uint32_t* b) {
    asm volatile(
        "mma.sync.aligned.m16n8k16.row.col.f32.bf16.bf16.f32 "
        "{%0,%1,%2,%3}, {%4,%5,%6,%7}, {%8,%9}, {%0,%1,%2,%3};"
        : "+f"(c[0]), "+f"(c[1]), "+f"(c[2]), "+f"(c[3])
        : "r"(a[0]), "r"(a[1]), "r"(a[2]), "r"(a[3]), "r"(b[0]), "r"(b[1]));
}

// ==================== bf16x3 tensor-core GEMM (mma.sync) ====================
template<int KFULL, int NHALF>
__global__ __launch_bounds__(256, 1)
void gemm_mma_bf16x3(const float* __restrict__ A,
                     const float* __restrict__ Wl, const float* __restrict__ Wr,
                     __half* __restrict__ Hl, float* __restrict__ Cr, int M) {
    constexpr int NC   = KFULL / 64;
    constexpr uint32_t A_LO = 18432;             // 128*144
    constexpr uint32_t B_HI = 36864;             // A hi+lo
    constexpr uint32_t B_LO = 17408;             // 64*272
    constexpr uint32_t BUF  = 36864 + 2 * 17408; // 71680

    extern __shared__ char smem[];
    const uint32_t sb = smem_to_u32(smem);

    const int tid = threadIdx.x;
    const int wid = tid >> 5;
    const int l   = tid & 31;
    const int wr  = wid >> 2;
    const int wc  = wid & 3;
    const int m0  = blockIdx.x * 128;
    const int z   = blockIdx.z;

    float acc[4][4][4];
    #pragma unroll
    for (int i = 0; i < 4; i++)
        #pragma unroll
        for (int j = 0; j < 4; j++)
            #pragma unroll
            for (int q = 0; q < 4; q++) acc[i][j][q] = 0.0f;

    auto fillA = [&](int c, uint32_t bufb) {
        const int k0 = c * 64;
        #pragma unroll
        for (int i = 0; i < 8; i++) {
            int fid = tid + i * 256;
            int r   = fid >> 4;
            int c4  = fid & 15;
            float4 v = make_float4(0.f, 0.f, 0.f, 0.f);
            int gr = m0 + r;
            if (gr < M)
                v = *(const float4*)(A + (size_t)gr * KFULL + k0 + c4 * 4);
            __nv_bfloat16 h0 = __float2bfloat16(v.x), h1 = __float2bfloat16(v.y);
            __nv_bfloat16 h2 = __float2bfloat16(v.z), h3 = __float2bfloat16(v.w);
            __nv_bfloat16 l0 = __float2bfloat16(v.x - __bfloat162float(h0));
            __nv_bfloat16 l1 = __float2bfloat16(v.y - __bfloat162float(h1));
            __nv_bfloat16 l2 = __float2bfloat16(v.z - __bfloat162float(h2));
            __nv_bfloat16 l3 = __float2bfloat16(v.w - __bfloat162float(h3));
            uint32_t addr = bufb + (uint32_t)r * 144 + (uint32_t)c4 * 8;
            sts32(addr,            pack_bf16(h0, h1));
            sts32(addr + 4,        pack_bf16(h2, h3));
            sts32(addr + A_LO,     pack_bf16(l0, l1));
            sts32(addr + A_LO + 4, pack_bf16(l2, l3));
        }
    };

    auto fillB = [&](int c, uint32_t bufb) {
        const int k0 = c * 64;
        #pragma unroll
        for (int i = 0; i < 8; i++) {
            int fid = tid + i * 256;
            int k   = fid >> 5;
            int n0  = (fid & 31) * 4;
            int gc  = z * 128 + n0;
            const float* Wp = (gc < NHALF) ? Wl : Wr;
            int col = (gc < NHALF) ? gc : gc - NHALF;
            float4 v = *(const float4*)(Wp + (size_t)(k0 + k) * NHALF + col);
            __nv_bfloat16 h0 = __float2bfloat16(v.x), h1 = __float2bfloat16(v.y);
            __nv_bfloat16 h2 = __float2bfloat16(v.z), h3 = __float2bfloat16(v.w);
            __nv_bfloat16 l0 = __float2bfloat16(v.x - __bfloat162float(h0));
            __nv_bfloat16 l1 = __float2bfloat16(v.y - __bfloat162float(h1));
            __nv_bfloat16 l2 = __float2bfloat16(v.z - __bfloat162float(h2));
            __nv_bfloat16 l3 = __float2bfloat16(v.w - __bfloat162float(h3));
            uint32_t addr = bufb + B_HI + (uint32_t)k * 272 + (uint32_t)n0 * 2;
            sts32(addr,            pack_bf16(h0, h1));
            sts32(addr + 4,        pack_bf16(h2, h3));
            sts32(addr + B_LO,     pack_bf16(l0, l1));
            sts32(addr + B_LO + 4, pack_bf16(l2, l3));
        }
    };

    auto compute = [&](uint32_t bufb) {
        const uint32_t aBase = bufb + ((uint32_t)(wr * 64 + (l >> 2))) * 144 + (uint32_t)(l & 3) * 4;
        const uint32_t bBase = bufb + B_HI + ((uint32_t)((l & 3) * 2)) * 272
                             + ((uint32_t)(wc * 32 + (l >> 2))) * 2;
        #pragma unroll
        for (int ks = 0; ks < 4; ks++) {
            uint32_t ah[4][4], al[4][4], bh[4][2], bl[4][2];
            #pragma unroll
            for (int mf = 0; mf < 4; mf++) {
                uint32_t a0 = aBase + (uint32_t)mf * 2304 + (uint32_t)ks * 32;
                ah[mf][0] = lds32(a0);
                ah[mf][1] = lds32(a0 + 1152);
                ah[mf][2] = lds32(a0 + 16);
                ah[mf][3] = lds32(a0 + 1152 + 16);
                al[mf][0] = lds32(a0 + A_LO);
                al[mf][1] = lds32(a0 + A_LO + 1152);
                al[mf][2] = lds32(a0 + A_LO + 16);
                al[mf][3] = lds32(a0 + A_LO + 1152 + 16);
            }
            #pragma unroll
            for (int nf = 0; nf < 4; nf++) {
                uint32_t b0 = bBase + (uint32_t)ks * 4352 + (uint32_t)nf * 16;
                bh[nf][0] = lds16(b0)        | (lds16(b0 + 272)  << 16);
                bh[nf][1] = lds16(b0 + 2176) | (lds16(b0 + 2448) << 16);
                bl[nf][0] = lds16(b0 + B_LO)        | (lds16(b0 + B_LO + 272)  << 16);
                bl[nf][1] = lds16(b0 + B_LO + 2176) | (lds16(b0 + B_LO + 2448) << 16);
            }
            #pragma unroll
            for (int mf = 0; mf < 4; mf++)
                #pragma unroll
                for (int nf = 0; nf < 4; nf++) {
                    mma16816(acc[mf][nf], ah[mf], bh[nf]);
                    mma16816(acc[mf][nf], ah[mf], bl[nf]);
                    mma16816(acc[mf][nf], al[mf], bh[nf]);
                }
        }
    };

    fillA(0, sb); fillB(0, sb);
    __syncthreads();
    #pragma unroll
    for (int c = 0; c < NC; c++) {
        uint32_t cur = sb + (uint32_t)(c & 1) * BUF;
        if (c + 1 < NC) {
            uint32_t nxt = sb + (uint32_t)((c + 1) & 1) * BUF;
            fillA(c + 1, nxt); fillB(c + 1, nxt);
        }
        compute(cur);
        __syncthreads();
    }

    #pragma unroll
    for (int mf = 0; mf < 4; mf++) {
        int r0 = m0 + wr * 64 + mf * 16 + (l >> 2);
        #pragma unroll
        for (int nf = 0; nf < 4; nf++) {
            int colL = wc * 32 + nf * 8 + (l & 3) * 2;
            int gc = z * 128 + colL;
            bool selL = gc < NHALF;
            int ch = selL ? gc : gc - NHALF;
            if (r0 < M) {
                if (selL)
                    *(__half2*)(Hl + (size_t)r0 * NHALF + ch) =
                        __floats2half2_rn(acc[mf][nf][0], acc[mf][nf][1]);
                else
                    *(float2*)(Cr + (size_t)r0 * NHALF + ch) =
                        make_float2(acc[mf][nf][0], acc[mf][nf][1]);
            }
            if (r0 + 8 < M) {
                if (selL)
                    *(__half2*)(Hl + (size_t)(r0 + 8) * NHALF + ch) =
                        __floats2half2_rn(acc[mf][nf][2], acc[mf][nf][3]);
                else
                    *(float2*)(Cr + (size_t)(r0 + 8) * NHALF + ch) =
                        make_float2(acc[mf][nf][2], acc[mf][nf][3]);
            }
        }
    }
}

// ==================== CSR build ==============================================
__global__ void zero_deg_kernel() {
    int i = blockIdx.x * blockDim.x + threadIdx.x;
    if (i < N_NODES) g_deg[i] = 0;
}

__global__ void hist_kernel(const int* __restrict__ dst, int E) {
    int i = (blockIdx.x * blockDim.x + threadIdx.x) * 8;
    if (i >= E) return;
    if (i + 8 <= E) {
        int4 d0 = *(const int4*)(dst + i);
        int4 d1 = *(const int4*)(dst + i + 4);
        atomicAdd(&g_deg[d0.x], 1); atomicAdd(&g_deg[d0.y], 1);
        atomicAdd(&g_deg[d0.z], 1); atomicAdd(&g_deg[d0.w], 1);
        atomicAdd(&g_deg[d1.x], 1); atomicAdd(&g_deg[d1.y], 1);
        atomicAdd(&g_deg[d1.z], 1); atomicAdd(&g_deg[d1.w], 1);
    } else {
        for (int e = i; e < E; e++) atomicAdd(&g_deg[dst[e]], 1);
    }
}

// single-block exclusive scan, warp-shuffle based
__global__ void scan_kernel(int E) {
    __shared__ int wsums[32];
    __shared__ int carry_sh;
    const int lane = threadIdx.x & 31;
    const int w    = threadIdx.x >> 5;
    if (threadIdx.x == 0) carry_sh = 0;
    __syncthreads();
    for (int base = 0; base < N_NODES; base += 1024) {
        int i = base + (int)threadIdx.x;
        int v = (i < N_NODES) ? g_deg[i] : 0;
        int x = v;
        #pragma unroll
        for (int o = 1; o < 32; o <<= 1) {
            int t = __shfl_up_sync(0xFFFFFFFFu, x, o);
            if (lane >= o) x += t;
        }
        if (lane == 31) wsums[w] = x;
        __syncthreads();
        if (w == 0) {
            int y = wsums[lane];
            #pragma unroll
            for (int o = 1; o < 32; o <<= 1) {
                int u = __shfl_up_sync(0xFFFFFFFFu, y, o);
                if (lane >= o) y += u;
            }
            wsums[lane] = y;
        }
        __syncthreads();
        int warpoff = (w == 0) ? 0 : wsums[w - 1];
        int incl = x + warpoff + carry_sh;
        if (i < N_NODES) { g_rowptr[i] = incl - v; g_wp[i] = incl - v; }
        __syncthreads();
        if (threadIdx.x == 1023) carry_sh = incl;
        __syncthreads();
    }
    if (threadIdx.x == 0) g_rowptr[N_NODES] = E;
}

__global__ void scatter_kernel(const int* __restrict__ src, const int* __restrict__ dst, int E) {
    int i = (blockIdx.x * blockDim.x + threadIdx.x) * 8;
    if (i >= E) return;
    if (i + 8 <= E) {
        int4 s0 = *(const int4*)(src + i);
        int4 s1 = *(const int4*)(src + i + 4);
        int4 d0 = *(const int4*)(dst + i);
        int4 d1 = *(const int4*)(dst + i + 4);
        int p0 = atomicAdd(&g_wp[d0.x], 1);
        int p1 = atomicAdd(&g_wp[d0.y], 1);
        int p2 = atomicAdd(&g_wp[d0.z], 1);
        int p3 = atomicAdd(&g_wp[d0.w], 1);
        int p4 = atomicAdd(&g_wp[d1.x], 1);
        int p5 = atomicAdd(&g_wp[d1.y], 1);
        int p6 = atomicAdd(&g_wp[d1.z], 1);
        int p7 = atomicAdd(&g_wp[d1.w], 1);
        g_csrc[p0] = s0.x; g_csrc[p1] = s0.y; g_csrc[p2] = s0.z; g_csrc[p3] = s0.w;
        g_csrc[p4] = s1.x; g_csrc[p5] = s1.y; g_csrc[p6] = s1.z; g_csrc[p7] = s1.w;
    } else {
        for (int e = i; e < E; e++) {
            int pos = atomicAdd(&g_wp[dst[e]], 1);
            g_csrc[pos] = src[e];
        }
    }
}

// ==================== fused GATv2 edge phase ==================================
// Sub-warp groups: F/8 lanes per edge, each lane covers 8 features (uint4 load).
// 2 edges in flight per group -> 2*NG edges in flight per warp.
template<int F, bool RELU>
__global__ void gat_aggregate_kernel(const __half* __restrict__ xl,
                                     const float* __restrict__ xr,
                                     const float* __restrict__ att,
                                     const float* __restrict__ bias,
                                     float* __restrict__ out) {
    constexpr int GS = F / 8;      // lanes per edge group (16 for F=128, 8 for F=64)
    constexpr int NG = 32 / GS;    // groups per warp (2 or 4)
    int n    = (blockIdx.x * blockDim.x + threadIdx.x) >> 5;
    int lane = threadIdx.x & 31;
    if (n >= N_NODES) return;
    const int gid = lane / GS;
    const int f0  = (lane % GS) * 8;

    float xrv[8], attv[8], acc[8];
    #pragma unroll
    for (int k = 0; k < 8; k++) {
        xrv[k]  = xr[(size_t)n * F + f0 + k];
        attv[k] = att[f0 + k];
        acc[k]  = 0.0f;
    }
    float s = 0.0f;

    const int start = g_rowptr[n];
    const int end   = g_rowptr[n + 1];

    auto unpack = [](uint4 u, float* v) {
        float2 a = __half22float2(*(const __half2*)&u.x);
        float2 b = __half22float2(*(const __half2*)&u.y);
        float2 c = __half22float2(*(const __half2*)&u.z);
        float2 d = __half22float2(*(const __half2*)&u.w);
        v[0] = a.x; v[1] = a.y; v[2] = b.x; v[3] = b.y;
        v[4] = c.x; v[5] = c.y; v[6] = d.x; v[7] = d.y;
    };

    for (int base = start; base < end; base += 32) {
        int myid = (base + lane < end) ? g_csrc[base + lane] : 0;
        int cnt  = min(32, end - base);
        for (int j = 0; j < cnt; j += 2 * NG) {
            int i0 = j + 2 * gid;
            int i1 = i0 + 1;
            int sn0 = __shfl_sync(0xFFFFFFFFu, myid, min(i0, cnt - 1));
            int sn1 = __shfl_sync(0xFFFFFFFFu, myid, min(i1, cnt - 1));
            bool a0 = i0 < cnt, a1 = i1 < cnt;
            uint4 u0 = *(const uint4*)(xl + (size_t)sn0 * F + f0);
            uint4 u1 = *(const uint4*)(xl + (size_t)sn1 * F + f0);
            float v0[8], v1[8];
            unpack(u0, v0);
            unpack(u1, v1);
            float p0 = 0.0f, p1 = 0.0f;
            #pragma unroll
            for (int k = 0; k < 8; k++) {
                float z0 = v0[k] + xrv[k];
                float z1 = v1[k] + xrv[k];
                float lz0 = z0 > 0.0f ? z0 : NEG_SLOPE * z0;
                float lz1 = z1 > 0.0f ? z1 : NEG_SLOPE * z1;
                p0 = fmaf(attv[k], lz0, p0);
                p1 = fmaf(attv[k], lz1, p1);
            }
            #pragma unroll
            for (int o = GS / 2; o > 0; o >>= 1) {
                p0 += __shfl_xor_sync(0xFFFFFFFFu, p0, o);
                p1 += __shfl_xor_sync(0xFFFFFFFFu, p1, o);
            }
            float e0 = a0 ? __expf(p0) : 0.0f;
            float e1 = a1 ? __expf(p1) : 0.0f;
            s += e0 + e1;
            #pragma unroll
            for (int k = 0; k < 8; k++)
                acc[k] = fmaf(e0, v0[k], fmaf(e1, v1[k], acc[k]));
        }
    }

    // combine groups (xor across group boundaries)
    #pragma unroll
    for (int o = GS; o < 32; o <<= 1) {
        s += __shfl_xor_sync(0xFFFFFFFFu, s, o);
        #pragma unroll
        for (int k = 0; k < 8; k++)
            acc[k] += __shfl_xor_sync(0xFFFFFFFFu, acc[k], o);
    }

    if (gid == 0) {
        float inv = 1.0f / (s + EPS_F);
        float o0[8];
        #pragma unroll
        for (int k = 0; k < 8; k++) {
            float v = acc[k] * inv + bias[f0 + k];
            o0[k] = RELU ? (v > 0.0f ? v : 0.0f) : v;
        }
        float* dp = out + (size_t)n * F + f0;
        *(float4*)(dp)     = make_float4(o0[0], o0[1], o0[2], o0[3]);
        *(float4*)(dp + 4) = make_float4(o0[4], o0[5], o0[6], o0[7]);
    }
}

// ==================== launch =================================================
extern "C" void kernel_launch(void* const* d_in, const int* in_sizes, int n_in,
                              void* d_out, int out_size) {
    const float* x    = (const float*)d_in[0];
    const int*   ei   = (const int*)  d_in[1];
    const float* Wl1  = (const float*)d_in[2];
    const float* Wr1  = (const float*)d_in[3];
    const float* att1 = (const float*)d_in[4];
    const float* b1   = (const float*)d_in[5];
    const float* Wl2  = (const float*)d_in[6];
    const float* Wr2  = (const float*)d_in[7];
    const float* att2 = (const float*)d_in[8];
    const float* b2   = (const float*)d_in[9];
    float* out = (float*)d_out;

    const int E = in_sizes[1] / 2;
    const int* src = ei;
    const int* dst = ei + E;

    __half *p_xl1h, *p_xl2h;
    float *p_xr1, *p_h, *p_xr2;
    cudaGetSymbolAddress((void**)&p_xl1h, g_xl1h);
    cudaGetSymbolAddress((void**)&p_xr1,  g_xr1);
    cudaGetSymbolAddress((void**)&p_h,    g_h);
    cudaGetSymbolAddress((void**)&p_xl2h, g_xl2h);
    cudaGetSymbolAddress((void**)&p_xr2,  g_xr2);

    const int SMEM = 2 * 71680;
    cudaFuncSetAttribute(gemm_mma_bf16x3<F_IN,  H_DIM>,
                         cudaFuncAttributeMaxDynamicSharedMemorySize, SMEM);
    cudaFuncSetAttribute(gemm_mma_bf16x3<H_DIM, C_DIM>,
                         cudaFuncAttributeMaxDynamicSharedMemorySize, SMEM);

    const int TILES = (N_NODES + 127) / 128;
    const int Q8 = (E + 7) / 8;

    // ---- CSR build ----
    zero_deg_kernel<<<(N_NODES + 255) / 256, 256>>>();
    hist_kernel<<<(Q8 + 255) / 256, 256>>>(dst, E);
    scan_kernel<<<1, 1024>>>(E);
    scatter_kernel<<<(Q8 + 255) / 256, 256>>>(src, dst, E);

    // ---- layer 1 ----
    {
        dim3 grid(TILES, 1, 2);
        gemm_mma_bf16x3<F_IN, H_DIM><<<grid, 256, SMEM>>>(x, Wl1, Wr1, p_xl1h, p_xr1, N_NODES);
    }
    gat_aggregate_kernel<128, true><<<(N_NODES + 7) / 8, 256>>>(
        p_xl1h, p_xr1, att1, b1, p_h);

    // ---- layer 2 ----
    {
        dim3 grid(TILES, 1, 1);
        gemm_mma_bf16x3<H_DIM, C_DIM><<<grid, 256, SMEM>>>(p_h, Wl2, Wr2, p_xl2h, p_xr2, N_NODES);
    }
    gat_aggregate_kernel<64, false><<<(N_NODES + 7) / 8, 256>>>(
        p_xl2h, p_xr2, att2, b2, out);
}

// round 7
// speedup vs baseline: 3.4891x; 1.2018x over previous
#include <cuda_runtime.h>
#include <cuda_fp16.h>
#include <math_constants.h>
#include <cstdint>

#define N_NODES 50000
#define F_IN    256
#define H_DIM   128
#define C_DIM   64
#define E_MAX   1600000
#define NEG_SLOPE 0.2f
#define EPS_F 1e-16f

// ---------------- scratch (device globals; no allocation allowed) ----------
__device__ __half g_xl1h[N_NODES * H_DIM];   // fp16 source-side features (layer1)
__device__ float  g_xr1 [N_NODES * H_DIM];
__device__ float  g_h   [N_NODES * H_DIM];   // layer1 output / layer2 input
__device__ __half g_xl2h[N_NODES * C_DIM];
__device__ float  g_xr2 [N_NODES * C_DIM];
__device__ int    g_deg[N_NODES];
__device__ int    g_rowptr[N_NODES + 1];
__device__ int    g_wp [N_NODES];
__device__ int    g_csrc[E_MAX];             // src ids grouped by dst

// ==================== small asm helpers =====================================
__device__ __forceinline__ uint32_t smem_to_u32(const void* p) {
    uint32_t a;
    asm("{ .reg .u64 t; cvta.to.shared.u64 t, %1; cvt.u32.u64 %0, t; }"
        : "=r"(a) : "l"(p));
    return a;
}
__device__ __forceinline__ void sts64(uint32_t a, uint32_t v0, uint32_t v1) {
    asm volatile("st.shared.v2.b32 [%0], {%1, %2};" :: "r"(a), "r"(v0), "r"(v1) : "memory");
}
__device__ __forceinline__ void ldsm_x4(uint32_t* r, uint32_t addr) {
    asm volatile("ldmatrix.sync.aligned.m8n8.x4.shared.b16 {%0,%1,%2,%3}, [%4];"
        : "=r"(r[0]), "=r"(r[1]), "=r"(r[2]), "=r"(r[3]) : "r"(addr));
}
__device__ __forceinline__ void ldsm_x4_trans(uint32_t* r, uint32_t addr) {
    asm volatile("ldmatrix.sync.aligned.m8n8.x4.trans.shared.b16 {%0,%1,%2,%3}, [%4];"
        : "=r"(r[0]), "=r"(r[1]), "=r"(r[2]), "=r"(r[3]) : "r"(addr));
}
__device__ __forceinline__ void mma16816h(float* c, const uint32_t* a, const uint32_t* b) {
    asm volatile(
        "mma.sync.aligned.m16n8k16.row.col.f32.f16.f16.f32 "
        "{%0,%1,%2,%3}, {%4,%5,%6,%7}, {%8,%9}, {%0,%1,%2,%3};"
        : "+f"(c[0]), "+f"(c[1]), "+f"(c[2]), "+f"(c[3])
        : "r"(a[0]), "r"(a[1]), "r"(a[2]), "r"(a[3]), "r"(b[0]), "r"(b[1]));
}

// ==================== fp16 tensor-core GEMM (mma.sync + ldmatrix) ===========
// C[:, z*128 .. z*128+127] over fused [Wl | Wr]. BM=128, BN=128, BK=64.
// A smem: [128][64] fp16, pitch 144 B. B smem: [64][128] fp16 k-major, pitch 272 B.
// Left-half (Wl) columns stored fp16 into Hl; right half fp32 into Cr.
template<int KFULL, int NHALF>
__global__ __launch_bounds__(256, 2)
void gemm_mma_fp16(const float* __restrict__ A,
                   const float* __restrict__ Wl, const float* __restrict__ Wr,
                   __half* __restrict__ Hl, float* __restrict__ Cr, int M) {
    constexpr int NC = KFULL / 64;
    constexpr uint32_t BOFF = 18432;             // 128*144
    constexpr uint32_t BUF  = 18432 + 17408;     // + 64*272 = 35840

    extern __shared__ char smem[];
    const uint32_t sb = smem_to_u32(smem);

    const int tid = threadIdx.x;
    const int wid = tid >> 5;
    const int l   = tid & 31;
    const int wr  = wid >> 2;   // 0..1 (m half)
    const int wc  = wid & 3;    // 0..3 (n quarter)
    const int m0  = blockIdx.x * 128;
    const int z   = blockIdx.z;

    float acc[4][4][4];
    #pragma unroll
    for (int i = 0; i < 4; i++)
        #pragma unroll
        for (int j = 0; j < 4; j++)
            #pragma unroll
            for (int q = 0; q < 4; q++) acc[i][j][q] = 0.0f;

    auto fillA = [&](int c, uint32_t bufb) {
        const int k0 = c * 64;
        #pragma unroll
        for (int i = 0; i < 8; i++) {
            int fid = tid + i * 256;
            int r   = fid >> 4;
            int c4  = fid & 15;
            float4 v = make_float4(0.f, 0.f, 0.f, 0.f);
            int gr = m0 + r;
            if (gr < M)
                v = *(const float4*)(A + (size_t)gr * KFULL + k0 + c4 * 4);
            __half2 h01 = __floats2half2_rn(v.x, v.y);
            __half2 h23 = __floats2half2_rn(v.z, v.w);
            sts64(bufb + (uint32_t)r * 144 + (uint32_t)c4 * 8,
                  *(uint32_t*)&h01, *(uint32_t*)&h23);
        }
    };

    auto fillB = [&](int c, uint32_t bufb) {
        const int k0 = c * 64;
        #pragma unroll
        for (int i = 0; i < 8; i++) {
            int fid = tid + i * 256;
            int k   = fid >> 5;
            int n0  = (fid & 31) * 4;
            int gc  = z * 128 + n0;
            const float* Wp = (gc < NHALF) ? Wl : Wr;
            int col = (gc < NHALF) ? gc : gc - NHALF;
            float4 v = *(const float4*)(Wp + (size_t)(k0 + k) * NHALF + col);
            __half2 h01 = __floats2half2_rn(v.x, v.y);
            __half2 h23 = __floats2half2_rn(v.z, v.w);
            sts64(bufb + BOFF + (uint32_t)k * 272 + (uint32_t)n0 * 2,
                  *(uint32_t*)&h01, *(uint32_t*)&h23);
        }
    };

    auto compute = [&](uint32_t bufb) {
        const uint32_t aLane = bufb + ((uint32_t)(wr * 64 + (l & 15))) * 144
                             + (uint32_t)((l >> 4) & 1) * 16;
        const uint32_t bLane = bufb + BOFF + (uint32_t)(l & 15) * 272
                             + (uint32_t)((l >> 4) & 1) * 16
                             + (uint32_t)(wc * 32) * 2;
        #pragma unroll
        for (int ks = 0; ks < 4; ks++) {
            uint32_t af[4][4], bf[2][4];
            #pragma unroll
            for (int mf = 0; mf < 4; mf++)
                ldsm_x4(af[mf], aLane + (uint32_t)mf * 2304 + (uint32_t)ks * 32);
            #pragma unroll
            for (int p = 0; p < 2; p++)
                ldsm_x4_trans(bf[p], bLane + (uint32_t)ks * 4352 + (uint32_t)p * 32);
            #pragma unroll
            for (int mf = 0; mf < 4; mf++)
                #pragma unroll
                for (int nf = 0; nf < 4; nf++)
                    mma16816h(acc[mf][nf], af[mf], &bf[nf >> 1][(nf & 1) * 2]);
        }
    };

    fillA(0, sb); fillB(0, sb);
    __syncthreads();
    #pragma unroll
    for (int c = 0; c < NC; c++) {
        uint32_t cur = sb + (uint32_t)(c & 1) * BUF;
        if (c + 1 < NC) {
            uint32_t nxt = sb + (uint32_t)((c + 1) & 1) * BUF;
            fillA(c + 1, nxt); fillB(c + 1, nxt);
        }
        compute(cur);
        __syncthreads();
    }

    // ---- epilogue: left half -> fp16 Hl, right half -> fp32 Cr --------------
    #pragma unroll
    for (int mf = 0; mf < 4; mf++) {
        int r0 = m0 + wr * 64 + mf * 16 + (l >> 2);
        #pragma unroll
        for (int nf = 0; nf < 4; nf++) {
            int colL = wc * 32 + nf * 8 + (l & 3) * 2;
            int gc = z * 128 + colL;
            bool selL = gc < NHALF;
            int ch = selL ? gc : gc - NHALF;
            if (r0 < M) {
                if (selL)
                    *(__half2*)(Hl + (size_t)r0 * NHALF + ch) =
                        __floats2half2_rn(acc[mf][nf][0], acc[mf][nf][1]);
                else
                    *(float2*)(Cr + (size_t)r0 * NHALF + ch) =
                        make_float2(acc[mf][nf][0], acc[mf][nf][1]);
            }
            if (r0 + 8 < M) {
                if (selL)
                    *(__half2*)(Hl + (size_t)(r0 + 8) * NHALF + ch) =
                        __floats2half2_rn(acc[mf][nf][2], acc[mf][nf][3]);
                else
                    *(float2*)(Cr + (size_t)(r0 + 8) * NHALF + ch) =
                        make_float2(acc[mf][nf][2], acc[mf][nf][3]);
            }
        }
    }
}

// ==================== CSR build ==============================================
__global__ void zero_deg_kernel() {
    int i = blockIdx.x * blockDim.x + threadIdx.x;
    if (i < N_NODES) g_deg[i] = 0;
}

__global__ void hist_kernel(const int* __restrict__ dst, int E) {
    int i = (blockIdx.x * blockDim.x + threadIdx.x) * 4;
    if (i >= E) return;
    if (i + 4 <= E) {
        int4 d = *(const int4*)(dst + i);
        atomicAdd(&g_deg[d.x], 1);
        atomicAdd(&g_deg[d.y], 1);
        atomicAdd(&g_deg[d.z], 1);
        atomicAdd(&g_deg[d.w], 1);
    } else {
        for (int e = i; e < E; e++) atomicAdd(&g_deg[dst[e]], 1);
    }
}

__global__ void scan_kernel(int E) {
    __shared__ int wsums[32];
    __shared__ int carry_sh;
    const int lane = threadIdx.x & 31;
    const int w    = threadIdx.x >> 5;
    if (threadIdx.x == 0) carry_sh = 0;
    __syncthreads();
    for (int base = 0; base < N_NODES; base += 1024) {
        int i = base + (int)threadIdx.x;
        int v = (i < N_NODES) ? g_deg[i] : 0;
        int x = v;
        #pragma unroll
        for (int o = 1; o < 32; o <<= 1) {
            int t = __shfl_up_sync(0xFFFFFFFFu, x, o);
            if (lane >= o) x += t;
        }
        if (lane == 31) wsums[w] = x;
        __syncthreads();
        if (w == 0) {
            int y = wsums[lane];
            #pragma unroll
            for (int o = 1; o < 32; o <<= 1) {
                int u = __shfl_up_sync(0xFFFFFFFFu, y, o);
                if (lane >= o) y += u;
            }
            wsums[lane] = y;
        }
        __syncthreads();
        int warpoff = (w == 0) ? 0 : wsums[w - 1];
        int incl = x + warpoff + carry_sh;
        if (i < N_NODES) { g_rowptr[i] = incl - v; g_wp[i] = incl - v; }
        __syncthreads();
        if (threadIdx.x == 1023) carry_sh = incl;
        __syncthreads();
    }
    if (threadIdx.x == 0) g_rowptr[N_NODES] = E;
}

__global__ void scatter_kernel(const int* __restrict__ src, const int* __restrict__ dst, int E) {
    int i = (blockIdx.x * blockDim.x + threadIdx.x) * 4;
    if (i >= E) return;
    if (i + 4 <= E) {
        int4 s = *(const int4*)(src + i);
        int4 d = *(const int4*)(dst + i);
        int p0 = atomicAdd(&g_wp[d.x], 1);
        int p1 = atomicAdd(&g_wp[d.y], 1);
        int p2 = atomicAdd(&g_wp[d.z], 1);
        int p3 = atomicAdd(&g_wp[d.w], 1);
        g_csrc[p0] = s.x; g_csrc[p1] = s.y; g_csrc[p2] = s.z; g_csrc[p3] = s.w;
    } else {
        for (int e = i; e < E; e++) {
            int pos = atomicAdd(&g_wp[dst[e]], 1);
            g_csrc[pos] = src[e];
        }
    }
}

// ==================== fused GATv2 edge phase ==================================
// Sub-warp groups: F/8 lanes per edge, each lane covers 8 features (uint4 load).
template<int F, bool RELU>
__global__ void gat_aggregate_kernel(const __half* __restrict__ xl,
                                     const float* __restrict__ xr,
                                     const float* __restrict__ att,
                                     const float* __restrict__ bias,
                                     float* __restrict__ out) {
    constexpr int GS = F / 8;
    constexpr int NG = 32 / GS;
    int n    = (blockIdx.x * blockDim.x + threadIdx.x) >> 5;
    int lane = threadIdx.x & 31;
    if (n >= N_NODES) return;
    const int gid = lane / GS;
    const int f0  = (lane % GS) * 8;

    float xrv[8], attv[8], acc[8];
    #pragma unroll
    for (int k = 0; k < 8; k++) {
        xrv[k]  = xr[(size_t)n * F + f0 + k];
        attv[k] = att[f0 + k];
        acc[k]  = 0.0f;
    }
    float s = 0.0f;

    const int start = g_rowptr[n];
    const int end   = g_rowptr[n + 1];

    auto unpack = [](uint4 u, float* v) {
        float2 a = __half22float2(*(const __half2*)&u.x);
        float2 b = __half22float2(*(const __half2*)&u.y);
        float2 c = __half22float2(*(const __half2*)&u.z);
        float2 d = __half22float2(*(const __half2*)&u.w);
        v[0] = a.x; v[1] = a.y; v[2] = b.x; v[3] = b.y;
        v[4] = c.x; v[5] = c.y; v[6] = d.x; v[7] = d.y;
    };

    for (int base = start; base < end; base += 32) {
        int myid = (base + lane < end) ? g_csrc[base + lane] : 0;
        int cnt  = min(32, end - base);
        for (int j = 0; j < cnt; j += 2 * NG) {
            int i0 = j + 2 * gid;
            int i1 = i0 + 1;
            int sn0 = __shfl_sync(0xFFFFFFFFu, myid, min(i0, cnt - 1));
            int sn1 = __shfl_sync(0xFFFFFFFFu, myid, min(i1, cnt - 1));
            bool a0 = i0 < cnt, a1 = i1 < cnt;
            uint4 u0 = *(const uint4*)(xl + (size_t)sn0 * F + f0);
            uint4 u1 = *(const uint4*)(xl + (size_t)sn1 * F + f0);
            float v0[8], v1[8];
            unpack(u0, v0);
            unpack(u1, v1);
            float p0 = 0.0f, p1 = 0.0f;
            #pragma unroll
            for (int k = 0; k < 8; k++) {
                float z0 = v0[k] + xrv[k];
                float z1 = v1[k] + xrv[k];
                float lz0 = z0 > 0.0f ? z0 : NEG_SLOPE * z0;
                float lz1 = z1 > 0.0f ? z1 : NEG_SLOPE * z1;
                p0 = fmaf(attv[k], lz0, p0);
                p1 = fmaf(attv[k], lz1, p1);
            }
            #pragma unroll
            for (int o = GS / 2; o > 0; o >>= 1) {
                p0 += __shfl_xor_sync(0xFFFFFFFFu, p0, o);
                p1 += __shfl_xor_sync(0xFFFFFFFFu, p1, o);
            }
            float e0 = a0 ? __expf(p0) : 0.0f;
            float e1 = a1 ? __expf(p1) : 0.0f;
            s += e0 + e1;
            #pragma unroll
            for (int k = 0; k < 8; k++)
                acc[k] = fmaf(e0, v0[k], fmaf(e1, v1[k], acc[k]));
        }
    }

    #pragma unroll
    for (int o = GS; o < 32; o <<= 1) {
        s += __shfl_xor_sync(0xFFFFFFFFu, s, o);
        #pragma unroll
        for (int k = 0; k < 8; k++)
            acc[k] += __shfl_xor_sync(0xFFFFFFFFu, acc[k], o);
    }

    if (gid == 0) {
        float inv = 1.0f / (s + EPS_F);
        float o0[8];
        #pragma unroll
        for (int k = 0; k < 8; k++) {
            float v = acc[k] * inv + bias[f0 + k];
            o0[k] = RELU ? (v > 0.0f ? v : 0.0f) : v;
        }
        float* dp = out + (size_t)n * F + f0;
        *(float4*)(dp)     = make_float4(o0[0], o0[1], o0[2], o0[3]);
        *(float4*)(dp + 4) = make_float4(o0[4], o0[5], o0[6], o0[7]);
    }
}

// ==================== launch =================================================
extern "C" void kernel_launch(void* const* d_in, const int* in_sizes, int n_in,
                              void* d_out, int out_size) {
    const float* x    = (const float*)d_in[0];
    const int*   ei   = (const int*)  d_in[1];
    const float* Wl1  = (const float*)d_in[2];
    const float* Wr1  = (const float*)d_in[3];
    const float* att1 = (const float*)d_in[4];
    const float* b1   = (const float*)d_in[5];
    const float* Wl2  = (const float*)d_in[6];
    const float* Wr2  = (const float*)d_in[7];
    const float* att2 = (const float*)d_in[8];
    const float* b2   = (const float*)d_in[9];
    float* out = (float*)d_out;

    const int E = in_sizes[1] / 2;
    const int* src = ei;
    const int* dst = ei + E;

    __half *p_xl1h, *p_xl2h;
    float *p_xr1, *p_h, *p_xr2;
    cudaGetSymbolAddress((void**)&p_xl1h, g_xl1h);
    cudaGetSymbolAddress((void**)&p_xr1,  g_xr1);
    cudaGetSymbolAddress((void**)&p_h,    g_h);
    cudaGetSymbolAddress((void**)&p_xl2h, g_xl2h);
    cudaGetSymbolAddress((void**)&p_xr2,  g_xr2);

    const int SMEM = 2 * 35840;   // 71680 double-buffered
    cudaFuncSetAttribute(gemm_mma_fp16<F_IN,  H_DIM>,
                         cudaFuncAttributeMaxDynamicSharedMemorySize, SMEM);
    cudaFuncSetAttribute(gemm_mma_fp16<H_DIM, C_DIM>,
                         cudaFuncAttributeMaxDynamicSharedMemorySize, SMEM);

    const int TILES = (N_NODES + 127) / 128;
    const int Q4 = (E + 3) / 4;

    // ---- CSR build ----
    zero_deg_kernel<<<(N_NODES + 255) / 256, 256>>>();
    hist_kernel<<<(Q4 + 255) / 256, 256>>>(dst, E);
    scan_kernel<<<1, 1024>>>(E);
    scatter_kernel<<<(Q4 + 255) / 256, 256>>>(src, dst, E);

    // ---- layer 1 ----
    {
        dim3 grid(TILES, 1, 2);
        gemm_mma_fp16<F_IN, H_DIM><<<grid, 256, SMEM>>>(x, Wl1, Wr1, p_xl1h, p_xr1, N_NODES);
    }
    gat_aggregate_kernel<128, true><<<(N_NODES + 7) / 8, 256>>>(
        p_xl1h, p_xr1, att1, b1, p_h);

    // ---- layer 2 ----
    {
        dim3 grid(TILES, 1, 1);
        gemm_mma_fp16<H_DIM, C_DIM><<<grid, 256, SMEM>>>(p_h, Wl2, Wr2, p_xl2h, p_xr2, N_NODES);
    }
    gat_aggregate_kernel<64, false><<<(N_NODES + 7) / 8, 256>>>(
        p_xl2h, p_xr2, att2, b2, out);
}